// round 1
// baseline (speedup 1.0000x reference)
#include <cuda_runtime.h>
#include <math.h>

#define N_NODES 100000
#define N_EDGES 3200000
#define F_IN    512
#define F_H     256
#define F_OUT   64

// ---------------- scratch (device globals: no alloc allowed) ----------------
__device__ int   g_deg[N_NODES];
__device__ int   g_cursor[N_NODES];
__device__ int   g_rowptr[N_NODES + 1];
__device__ float g_dis[N_NODES];
__device__ int   g_csr[N_EDGES];
__device__ float g_bufA[(size_t)N_NODES * F_H];
__device__ float g_bufB[(size_t)N_NODES * F_H];

// ---------------- CSR build ----------------
__global__ void zero_kernel() {
    int i = blockIdx.x * blockDim.x + threadIdx.x;
    if (i < N_NODES) { g_deg[i] = 0; g_cursor[i] = 0; }
}

__global__ void count_kernel(const int* __restrict__ ei) {
    int e = blockIdx.x * blockDim.x + threadIdx.x;
    if (e < N_EDGES) atomicAdd(&g_deg[ei[N_EDGES + e]], 1);
}

__global__ void dis_kernel() {
    int n = blockIdx.x * blockDim.x + threadIdx.x;
    if (n < N_NODES) g_dis[n] = rsqrtf((float)g_deg[n] + 1.0f);
}

// single-block exclusive scan of g_deg -> g_rowptr (N=100k, ~98 chunks of 1024)
__global__ void scan_kernel() {
    __shared__ int sh[1024];
    int tid = threadIdx.x;
    int run = 0;
    for (int base = 0; base < N_NODES; base += 1024) {
        int idx = base + tid;
        int v = (idx < N_NODES) ? g_deg[idx] : 0;
        sh[tid] = v;
        __syncthreads();
        #pragma unroll
        for (int off = 1; off < 1024; off <<= 1) {
            int t = (tid >= off) ? sh[tid - off] : 0;
            __syncthreads();
            sh[tid] += t;
            __syncthreads();
        }
        if (idx < N_NODES) g_rowptr[idx] = run + sh[tid] - v;  // exclusive
        run += sh[1023];
        __syncthreads();
    }
    if (tid == 0) g_rowptr[N_NODES] = run;
}

__global__ void scatter_kernel(const int* __restrict__ ei) {
    int e = blockIdx.x * blockDim.x + threadIdx.x;
    if (e < N_EDGES) {
        int d = ei[N_EDGES + e];
        int pos = atomicAdd(&g_cursor[d], 1);
        g_csr[g_rowptr[d] + pos] = ei[e];
    }
}

// ---------------- SGEMM: C[M,N] = A[M,K] @ W[K,N] ----------------
// BM=128, BN=64, BK=16, 256 threads, 8x4 microtile per thread.
__global__ void sgemm_kernel(const float* __restrict__ A, const float* __restrict__ W,
                             float* __restrict__ C, int M, int K, int N) {
    const int BM = 128, BN = 64, BK = 16;
    __shared__ float As[BK][BM];
    __shared__ float Bs[BK][BN];

    int tid = threadIdx.x;
    int tx = tid % 16;          // N dir: 16*4 = 64
    int ty = tid / 16;          // M dir: 16*8 = 128
    int bm = blockIdx.y * BM;
    int bn = blockIdx.x * BN;

    float acc[8][4];
    #pragma unroll
    for (int i = 0; i < 8; i++)
        #pragma unroll
        for (int j = 0; j < 4; j++) acc[i][j] = 0.f;

    for (int k0 = 0; k0 < K; k0 += BK) {
        // A tile: 128x16 floats = 512 float4, 2 per thread, store transposed
        #pragma unroll
        for (int it = 0; it < 2; it++) {
            int idx = tid + it * 256;          // float4 index
            int r  = idx >> 2;                 // row within tile [0,128)
            int kv = idx & 3;                  // float4 within row
            int grow = bm + r;
            float4 v = make_float4(0.f, 0.f, 0.f, 0.f);
            if (grow < M) v = *(const float4*)(A + (size_t)grow * K + k0 + kv * 4);
            As[kv * 4 + 0][r] = v.x;
            As[kv * 4 + 1][r] = v.y;
            As[kv * 4 + 2][r] = v.z;
            As[kv * 4 + 3][r] = v.w;
        }
        // B tile: 16x64 floats = 256 float4, 1 per thread
        {
            int r  = tid >> 4;                 // k row [0,16)
            int cv = tid & 15;                 // float4 col [0,16)
            *(float4*)&Bs[r][cv * 4] =
                *(const float4*)(W + (size_t)(k0 + r) * N + bn + cv * 4);
        }
        __syncthreads();

        #pragma unroll
        for (int kk = 0; kk < BK; kk++) {
            float a[8], b[4];
            *(float4*)&a[0] = *(float4*)&As[kk][ty * 8];
            *(float4*)&a[4] = *(float4*)&As[kk][ty * 8 + 4];
            *(float4*)&b[0] = *(float4*)&Bs[kk][tx * 4];
            #pragma unroll
            for (int i = 0; i < 8; i++)
                #pragma unroll
                for (int j = 0; j < 4; j++)
                    acc[i][j] = fmaf(a[i], b[j], acc[i][j]);
        }
        __syncthreads();
    }

    #pragma unroll
    for (int i = 0; i < 8; i++) {
        int row = bm + ty * 8 + i;
        if (row < M)
            *(float4*)(C + (size_t)row * N + bn + tx * 4) = *(float4*)&acc[i][0];
    }
}

// ---------------- aggregation: out = dis[n]*(sum_e dis[s]*h[s] + dis[n]*h[n]) + b ----------------
template<int F, bool RELU>
__global__ void agg_kernel(const float* __restrict__ h,
                           const float* __restrict__ bias,
                           float* __restrict__ out) {
    int node = blockIdx.x;
    int f = threadIdx.x;   // blockDim.x == F
    int beg = g_rowptr[node], end = g_rowptr[node + 1];
    float acc = 0.f;
    for (int e = beg; e < end; e++) {
        int s = g_csr[e];
        acc = fmaf(g_dis[s], __ldg(&h[(size_t)s * F + f]), acc);
    }
    float dn = g_dis[node];
    float v = dn * fmaf(dn, h[(size_t)node * F + f], acc) + bias[f];
    if (RELU) v = v > 0.f ? v : 0.01f * v;
    out[(size_t)node * F + f] = v;
}

// last layer: agg (F=64) fused with bias + softmax. 4 nodes per 256-thread block.
__global__ void agg_softmax_kernel(const float* __restrict__ h,
                                   const float* __restrict__ bias,
                                   float* __restrict__ out) {
    __shared__ float sh[256];
    int g = threadIdx.x / 64;
    int f = threadIdx.x % 64;
    int node = blockIdx.x * 4 + g;
    bool valid = node < N_NODES;

    float v = 0.f;
    if (valid) {
        int beg = g_rowptr[node], end = g_rowptr[node + 1];
        float acc = 0.f;
        for (int e = beg; e < end; e++) {
            int s = g_csr[e];
            acc = fmaf(g_dis[s], __ldg(&h[(size_t)s * 64 + f]), acc);
        }
        float dn = g_dis[node];
        v = dn * fmaf(dn, h[(size_t)node * 64 + f], acc) + bias[f];
    }

    // group max over 64 lanes
    sh[threadIdx.x] = valid ? v : -1e30f;
    __syncthreads();
    #pragma unroll
    for (int off = 32; off > 0; off >>= 1) {
        if (f < off) sh[threadIdx.x] = fmaxf(sh[threadIdx.x], sh[threadIdx.x + off]);
        __syncthreads();
    }
    float m = sh[g * 64];
    __syncthreads();

    float e = valid ? expf(v - m) : 0.f;
    sh[threadIdx.x] = e;
    __syncthreads();
    #pragma unroll
    for (int off = 32; off > 0; off >>= 1) {
        if (f < off) sh[threadIdx.x] += sh[threadIdx.x + off];
        __syncthreads();
    }
    float s = sh[g * 64];
    if (valid) out[(size_t)node * 64 + f] = e / s;
}

// ---------------- launch ----------------
extern "C" void kernel_launch(void* const* d_in, const int* in_sizes, int n_in,
                              void* d_out, int out_size) {
    const float* x  = (const float*)d_in[0];
    const int*   ei = (const int*)  d_in[1];
    const float* W0 = (const float*)d_in[2];
    const float* b0 = (const float*)d_in[3];
    const float* W1 = (const float*)d_in[4];
    const float* b1 = (const float*)d_in[5];
    const float* W2 = (const float*)d_in[6];
    const float* b2 = (const float*)d_in[7];
    const float* W3 = (const float*)d_in[8];
    const float* b3 = (const float*)d_in[9];
    float* out = (float*)d_out;

    float *bufA, *bufB;
    cudaGetSymbolAddress((void**)&bufA, g_bufA);
    cudaGetSymbolAddress((void**)&bufB, g_bufB);

    const int TB = 256;
    int nblk_nodes = (N_NODES + TB - 1) / TB;
    int nblk_edges = (N_EDGES + TB - 1) / TB;
    int mblocks = (N_NODES + 127) / 128;

    // CSR build (same every call -> deterministic work)
    zero_kernel<<<nblk_nodes, TB>>>();
    count_kernel<<<nblk_edges, TB>>>(ei);
    dis_kernel<<<nblk_nodes, TB>>>();
    scan_kernel<<<1, 1024>>>();
    scatter_kernel<<<nblk_edges, TB>>>(ei);

    // Layer 0: 512 -> 256
    sgemm_kernel<<<dim3(F_H / 64, mblocks), TB>>>(x, W0, bufA, N_NODES, F_IN, F_H);
    agg_kernel<F_H, true><<<N_NODES, F_H>>>(bufA, b0, bufB);

    // Layer 1: 256 -> 256
    sgemm_kernel<<<dim3(F_H / 64, mblocks), TB>>>(bufB, W1, bufA, N_NODES, F_H, F_H);
    agg_kernel<F_H, true><<<N_NODES, F_H>>>(bufA, b1, bufB);

    // Layer 2: 256 -> 256
    sgemm_kernel<<<dim3(F_H / 64, mblocks), TB>>>(bufB, W2, bufA, N_NODES, F_H, F_H);
    agg_kernel<F_H, true><<<N_NODES, F_H>>>(bufA, b2, bufB);

    // Layer 3: 256 -> 64, fused agg + bias + softmax
    sgemm_kernel<<<dim3(F_OUT / 64, mblocks), TB>>>(bufB, W3, bufA, N_NODES, F_H, F_OUT);
    agg_softmax_kernel<<<(N_NODES + 3) / 4, TB>>>(bufA, b3, out);
}

// round 4
// speedup vs baseline: 1.2669x; 1.2669x over previous
#include <cuda_runtime.h>
#include <cuda_bf16.h>
#include <math.h>
#include <cstdint>

#define N_NODES 100000
#define N_EDGES 3200000
#define F_IN    512
#define F_H     256
#define F_OUT   64

// ---------------- scratch (device globals: no alloc allowed) ----------------
__device__ int   g_deg[N_NODES];
__device__ int   g_cursor[N_NODES];
__device__ int   g_rowptr[N_NODES + 1];
__device__ float g_dis[N_NODES];
__device__ int   g_csr[N_EDGES];
__device__ int   g_blksum[128];
__device__ int   g_blkoff[128];
__device__ __nv_bfloat16 g_ahi[(size_t)N_NODES * F_IN];   // activation hi plane
__device__ __nv_bfloat16 g_alo[(size_t)N_NODES * F_IN];   // activation lo plane
__device__ float g_gout[(size_t)N_NODES * F_H];           // GEMM output (pre-agg) fp32
__device__ __nv_bfloat16 g_whi[4][(size_t)F_IN * F_H];    // W^T hi plane [N][K]
__device__ __nv_bfloat16 g_wlo[4][(size_t)F_IN * F_H];    // W^T lo plane [N][K]

// ---------------- packing helpers ----------------
__device__ __forceinline__ void split_bf16(float v, __nv_bfloat16& hi, __nv_bfloat16& lo) {
    hi = __float2bfloat16(v);
    lo = __float2bfloat16(v - __bfloat162float(hi));
}

__global__ void pack_x_kernel(const float* __restrict__ x,
                              __nv_bfloat16* __restrict__ hi,
                              __nv_bfloat16* __restrict__ lo, int n4) {
    int i = blockIdx.x * blockDim.x + threadIdx.x;
    if (i < n4) {
        float4 v = *(const float4*)(x + (size_t)i * 4);
        __nv_bfloat16 h0, l0, h1, l1, h2, l2, h3, l3;
        split_bf16(v.x, h0, l0); split_bf16(v.y, h1, l1);
        split_bf16(v.z, h2, l2); split_bf16(v.w, h3, l3);
        __nv_bfloat162 hh0 = __halves2bfloat162(h0, h1);
        __nv_bfloat162 hh1 = __halves2bfloat162(h2, h3);
        __nv_bfloat162 ll0 = __halves2bfloat162(l0, l1);
        __nv_bfloat162 ll1 = __halves2bfloat162(l2, l3);
        *(uint2*)(hi + (size_t)i * 4) = make_uint2(*(uint32_t*)&hh0, *(uint32_t*)&hh1);
        *(uint2*)(lo + (size_t)i * 4) = make_uint2(*(uint32_t*)&ll0, *(uint32_t*)&ll1);
    }
}

// W [K,N] fp32 -> W^T planes [N][K]
__global__ void pack_w_kernel(const float* __restrict__ W,
                              __nv_bfloat16* __restrict__ hi,
                              __nv_bfloat16* __restrict__ lo, int K, int N) {
    int i = blockIdx.x * blockDim.x + threadIdx.x;
    if (i < K * N) {
        int k = i / N, n = i % N;
        __nv_bfloat16 h, l;
        split_bf16(W[i], h, l);
        hi[(size_t)n * K + k] = h;
        lo[(size_t)n * K + k] = l;
    }
}

// ---------------- CSR build ----------------
__global__ void zero_kernel() {
    int i = blockIdx.x * blockDim.x + threadIdx.x;
    if (i < N_NODES) { g_deg[i] = 0; g_cursor[i] = 0; }
}
__global__ void count_kernel(const int* __restrict__ ei) {
    int e = blockIdx.x * blockDim.x + threadIdx.x;
    if (e < N_EDGES) atomicAdd(&g_deg[ei[N_EDGES + e]], 1);
}
__global__ void dis_kernel() {
    int n = blockIdx.x * blockDim.x + threadIdx.x;
    if (n < N_NODES) g_dis[n] = rsqrtf((float)g_deg[n] + 1.0f);
}
__global__ void scan1_kernel() {
    __shared__ int sh[1024];
    int tid = threadIdx.x;
    int idx = blockIdx.x * 1024 + tid;
    int v = (idx < N_NODES) ? g_deg[idx] : 0;
    sh[tid] = v;
    __syncthreads();
    #pragma unroll
    for (int off = 1; off < 1024; off <<= 1) {
        int t = (tid >= off) ? sh[tid - off] : 0;
        __syncthreads();
        sh[tid] += t;
        __syncthreads();
    }
    if (idx < N_NODES) g_rowptr[idx] = sh[tid] - v;
    if (tid == 1023) g_blksum[blockIdx.x] = sh[1023];
}
__global__ void scan2_kernel(int nblk) {
    if (threadIdx.x == 0) {
        int run = 0;
        for (int b = 0; b < nblk; b++) { int t = g_blksum[b]; g_blkoff[b] = run; run += t; }
        g_rowptr[N_NODES] = run;
    }
}
__global__ void scan3_kernel() {
    int idx = blockIdx.x * 1024 + threadIdx.x;
    if (idx < N_NODES) g_rowptr[idx] += g_blkoff[blockIdx.x];
}
__global__ void scatter_kernel(const int* __restrict__ ei) {
    int e = blockIdx.x * blockDim.x + threadIdx.x;
    if (e < N_EDGES) {
        int d = ei[N_EDGES + e];
        int pos = atomicAdd(&g_cursor[d], 1);
        g_csr[g_rowptr[d] + pos] = ei[e];
    }
}

// ---------------- mma.sync bf16 GEMM: C[M,N] = A[M,K] @ W[K,N] (W^T planes given) ----------------
// fp32 emulation: C = Ah*Bh + Ah*Bl + Al*Bh (bf16 hi/lo planes). BM=128 BN=64 BK=32.
// 8 warps: 4 in M x 2 in N, warp tile 32x32. cp.async double-buffered.
#define RS 20  /* smem row stride in u32 = 80 bytes */
__device__ __forceinline__ void cp_async16(uint32_t dst, const void* src, int szr) {
    asm volatile("cp.async.ca.shared.global [%0], [%1], 16, %2;"
                 :: "r"(dst), "l"(src), "r"(szr));
}
__device__ __forceinline__ void mma16816(float* c, const uint32_t* a, const uint32_t* b) {
    asm volatile(
        "mma.sync.aligned.m16n8k16.row.col.f32.bf16.bf16.f32 "
        "{%0,%1,%2,%3}, {%4,%5,%6,%7}, {%8,%9}, {%0,%1,%2,%3};"
        : "+f"(c[0]), "+f"(c[1]), "+f"(c[2]), "+f"(c[3])
        : "r"(a[0]), "r"(a[1]), "r"(a[2]), "r"(a[3]), "r"(b[0]), "r"(b[1]));
}

__global__ void __launch_bounds__(256)
mma_gemm_kernel(const __nv_bfloat16* __restrict__ Ahi, const __nv_bfloat16* __restrict__ Alo,
                const __nv_bfloat16* __restrict__ Bhi, const __nv_bfloat16* __restrict__ Blo,
                float* __restrict__ C, int M, int N, int K) {
    extern __shared__ char smem[];
    // per buffer: A_hi [0,10240) A_lo [10240,20480) B_hi [20480,25600) B_lo [25600,30720)
    const int BUF = 30720;
    uint32_t sbase;
    asm("{ .reg .u64 t; cvta.to.shared.u64 t, %1; cvt.u32.u64 %0, t; }"
        : "=r"(sbase) : "l"(smem));

    int tid = threadIdx.x, lane = tid & 31, wid = tid >> 5;
    int gID = lane >> 2, tig = lane & 3;
    int warpM = (wid & 3) * 32, warpN = (wid >> 2) * 32;
    int bm = blockIdx.y * 128, bn = blockIdx.x * 64;

    float acc[2][4][4];
    #pragma unroll
    for (int i = 0; i < 2; i++)
        #pragma unroll
        for (int j = 0; j < 4; j++)
            #pragma unroll
            for (int q = 0; q < 4; q++) acc[i][j][q] = 0.f;

    int nch = K >> 5;

    auto load_tile = [&](int buf, int c) {
        uint32_t bb = sbase + buf * BUF;
        // A: 2 planes x 128 rows x 4 chunks(16B) = 1024 cp.asyncs, 4 per thread
        #pragma unroll
        for (int it = 0; it < 4; it++) {
            int idx = tid + it * 256;
            int ch = idx & 3, r = (idx >> 2) & 127, pl = idx >> 9;
            int row = bm + r;
            int szr = (row < M) ? 16 : 0;
            int rowc = (row < M) ? row : (M - 1);   // clamp address; szr=0 suppresses read
            const __nv_bfloat16* src = (pl ? Alo : Ahi) + (size_t)rowc * K + c * 32 + ch * 8;
            cp_async16(bb + pl * 10240 + r * 80 + ch * 16, src, szr);
        }
        // B: 2 planes x 64 rows x 4 chunks = 512 cp.asyncs, 2 per thread
        #pragma unroll
        for (int it = 0; it < 2; it++) {
            int idx = tid + it * 256;
            int ch = idx & 3, r = (idx >> 2) & 63, pl = idx >> 8;
            const __nv_bfloat16* src = (pl ? Blo : Bhi) + (size_t)(bn + r) * K + c * 32 + ch * 8;
            cp_async16(bb + 20480 + pl * 5120 + r * 80 + ch * 16, src, 16);
        }
    };

    load_tile(0, 0);
    asm volatile("cp.async.commit_group;");

    for (int c = 0; c < nch; c++) {
        if (c + 1 < nch) load_tile((c + 1) & 1, c + 1);
        asm volatile("cp.async.commit_group;");
        asm volatile("cp.async.wait_group 1;");
        __syncthreads();

        const char* bufp = smem + (c & 1) * BUF;
        const uint32_t* sAh = (const uint32_t*)(bufp);
        const uint32_t* sAl = (const uint32_t*)(bufp + 10240);
        const uint32_t* sBh = (const uint32_t*)(bufp + 20480);
        const uint32_t* sBl = (const uint32_t*)(bufp + 25600);

        #pragma unroll
        for (int ks = 0; ks < 2; ks++) {
            int ko = ks * 8 + tig;  // u32 offset within row (k16 step)
            uint32_t ah[2][4], al[2][4], bh[4][2], bl[4][2];
            #pragma unroll
            for (int mt = 0; mt < 2; mt++) {
                int r0 = (warpM + mt * 16 + gID) * RS + ko;
                ah[mt][0] = sAh[r0];            ah[mt][1] = sAh[r0 + 8 * RS];
                ah[mt][2] = sAh[r0 + 4];        ah[mt][3] = sAh[r0 + 8 * RS + 4];
                al[mt][0] = sAl[r0];            al[mt][1] = sAl[r0 + 8 * RS];
                al[mt][2] = sAl[r0 + 4];        al[mt][3] = sAl[r0 + 8 * RS + 4];
            }
            #pragma unroll
            for (int nt = 0; nt < 4; nt++) {
                int r0 = (warpN + nt * 8 + gID) * RS + ko;
                bh[nt][0] = sBh[r0];  bh[nt][1] = sBh[r0 + 4];
                bl[nt][0] = sBl[r0];  bl[nt][1] = sBl[r0 + 4];
            }
            #pragma unroll
            for (int mt = 0; mt < 2; mt++)
                #pragma unroll
                for (int nt = 0; nt < 4; nt++) {
                    mma16816(acc[mt][nt], ah[mt], bh[nt]);
                    mma16816(acc[mt][nt], ah[mt], bl[nt]);
                    mma16816(acc[mt][nt], al[mt], bh[nt]);
                }
        }
        __syncthreads();
    }

    // epilogue: direct register -> global
    #pragma unroll
    for (int mt = 0; mt < 2; mt++) {
        int row0 = bm + warpM + mt * 16 + gID;
        #pragma unroll
        for (int nt = 0; nt < 4; nt++) {
            int col = bn + warpN + nt * 8 + tig * 2;
            if (row0 < M)
                *(float2*)(C + (size_t)row0 * N + col) = make_float2(acc[mt][nt][0], acc[mt][nt][1]);
            if (row0 + 8 < M)
                *(float2*)(C + (size_t)(row0 + 8) * N + col) = make_float2(acc[mt][nt][2], acc[mt][nt][3]);
        }
    }
}

// ---------------- aggregation: v = dis[n]*(sum dis[s]*h[s] + dis[n]*h[n]) + b; leaky; split planes ----------------
template<int F>
__global__ void agg_pack_kernel(const float* __restrict__ h,
                                const float* __restrict__ bias,
                                __nv_bfloat16* __restrict__ ohi,
                                __nv_bfloat16* __restrict__ olo) {
    int node = blockIdx.x;
    int f = threadIdx.x;
    int beg = g_rowptr[node], end = g_rowptr[node + 1];
    float acc = 0.f;
    for (int e = beg; e < end; e++) {
        int s = g_csr[e];
        acc = fmaf(g_dis[s], __ldg(&h[(size_t)s * F + f]), acc);
    }
    float dn = g_dis[node];
    float v = dn * fmaf(dn, h[(size_t)node * F + f], acc) + bias[f];
    v = v > 0.f ? v : 0.01f * v;
    __nv_bfloat16 hi, lo;
    split_bf16(v, hi, lo);
    ohi[(size_t)node * F + f] = hi;
    olo[(size_t)node * F + f] = lo;
}

// last layer: agg (F=64) fused with bias + softmax. 4 nodes per 256-thread block.
__global__ void agg_softmax_kernel(const float* __restrict__ h,
                                   const float* __restrict__ bias,
                                   float* __restrict__ out) {
    __shared__ float sh[256];
    int g = threadIdx.x / 64;
    int f = threadIdx.x % 64;
    int node = blockIdx.x * 4 + g;
    bool valid = node < N_NODES;

    float v = 0.f;
    if (valid) {
        int beg = g_rowptr[node], end = g_rowptr[node + 1];
        float acc = 0.f;
        for (int e = beg; e < end; e++) {
            int s = g_csr[e];
            acc = fmaf(g_dis[s], __ldg(&h[(size_t)s * 64 + f]), acc);
        }
        float dn = g_dis[node];
        v = dn * fmaf(dn, h[(size_t)node * 64 + f], acc) + bias[f];
    }
    sh[threadIdx.x] = valid ? v : -1e30f;
    __syncthreads();
    #pragma unroll
    for (int off = 32; off > 0; off >>= 1) {
        if (f < off) sh[threadIdx.x] = fmaxf(sh[threadIdx.x], sh[threadIdx.x + off]);
        __syncthreads();
    }
    float m = sh[g * 64];
    __syncthreads();
    float e = valid ? expf(v - m) : 0.f;
    sh[threadIdx.x] = e;
    __syncthreads();
    #pragma unroll
    for (int off = 32; off > 0; off >>= 1) {
        if (f < off) sh[threadIdx.x] += sh[threadIdx.x + off];
        __syncthreads();
    }
    float s = sh[g * 64];
    if (valid) out[(size_t)node * 64 + f] = e / s;
}

// ---------------- launch ----------------
extern "C" void kernel_launch(void* const* d_in, const int* in_sizes, int n_in,
                              void* d_out, int out_size) {
    const float* x  = (const float*)d_in[0];
    const int*   ei = (const int*)  d_in[1];
    const float* W0 = (const float*)d_in[2];
    const float* b0 = (const float*)d_in[3];
    const float* W1 = (const float*)d_in[4];
    const float* b1 = (const float*)d_in[5];
    const float* W2 = (const float*)d_in[6];
    const float* b2 = (const float*)d_in[7];
    const float* W3 = (const float*)d_in[8];
    const float* b3 = (const float*)d_in[9];
    float* out = (float*)d_out;

    __nv_bfloat16 *ahi, *alo, *whibase, *wlobase;
    float* gout;
    cudaGetSymbolAddress((void**)&ahi, g_ahi);
    cudaGetSymbolAddress((void**)&alo, g_alo);
    cudaGetSymbolAddress((void**)&whibase, g_whi);
    cudaGetSymbolAddress((void**)&wlobase, g_wlo);
    cudaGetSymbolAddress((void**)&gout, g_gout);
    const size_t WSTRIDE = (size_t)F_IN * F_H;

    cudaFuncSetAttribute(mma_gemm_kernel, cudaFuncAttributeMaxDynamicSharedMemorySize, 61440);

    const int TB = 256;
    int nblk_nodes = (N_NODES + TB - 1) / TB;
    int nblk_edges = (N_EDGES + TB - 1) / TB;
    int scan_blks = (N_NODES + 1023) / 1024;
    int mtiles = (N_NODES + 127) / 128;

    // CSR build
    zero_kernel<<<nblk_nodes, TB>>>();
    count_kernel<<<nblk_edges, TB>>>(ei);
    dis_kernel<<<nblk_nodes, TB>>>();
    scan1_kernel<<<scan_blks, 1024>>>();
    scan2_kernel<<<1, 32>>>(scan_blks);
    scan3_kernel<<<scan_blks, 1024>>>();
    scatter_kernel<<<nblk_edges, TB>>>(ei);

    // pack inputs / weights
    pack_x_kernel<<<(N_NODES * F_IN / 4 + TB - 1) / TB, TB>>>(x, ahi, alo, N_NODES * F_IN / 4);
    pack_w_kernel<<<(F_IN * F_H + TB - 1) / TB, TB>>>(W0, whibase, wlobase, F_IN, F_H);
    pack_w_kernel<<<(F_H * F_H + TB - 1) / TB, TB>>>(W1, whibase + WSTRIDE, wlobase + WSTRIDE, F_H, F_H);
    pack_w_kernel<<<(F_H * F_H + TB - 1) / TB, TB>>>(W2, whibase + 2 * WSTRIDE, wlobase + 2 * WSTRIDE, F_H, F_H);
    pack_w_kernel<<<(F_H * F_OUT + TB - 1) / TB, TB>>>(W3, whibase + 3 * WSTRIDE, wlobase + 3 * WSTRIDE, F_H, F_OUT);

    // Layer 0: 512 -> 256
    mma_gemm_kernel<<<dim3(4, mtiles), TB, 61440>>>(ahi, alo, whibase, wlobase, gout,
                                                    N_NODES, F_H, F_IN);
    agg_pack_kernel<F_H><<<N_NODES, F_H>>>(gout, b0, ahi, alo);
    // Layer 1
    mma_gemm_kernel<<<dim3(4, mtiles), TB, 61440>>>(ahi, alo, whibase + WSTRIDE, wlobase + WSTRIDE,
                                                    gout, N_NODES, F_H, F_H);
    agg_pack_kernel<F_H><<<N_NODES, F_H>>>(gout, b1, ahi, alo);
    // Layer 2
    mma_gemm_kernel<<<dim3(4, mtiles), TB, 61440>>>(ahi, alo, whibase + 2 * WSTRIDE, wlobase + 2 * WSTRIDE,
                                                    gout, N_NODES, F_H, F_H);
    agg_pack_kernel<F_H><<<N_NODES, F_H>>>(gout, b2, ahi, alo);
    // Layer 3: 256 -> 64 + softmax
    mma_gemm_kernel<<<dim3(1, mtiles), TB, 61440>>>(ahi, alo, whibase + 3 * WSTRIDE, wlobase + 3 * WSTRIDE,
                                                    gout, N_NODES, F_OUT, F_H);
    agg_softmax_kernel<<<(N_NODES + 3) / 4, TB>>>(gout, b3, out);
}

// round 5
// speedup vs baseline: 1.4703x; 1.1606x over previous
#include <cuda_runtime.h>
#include <cuda_bf16.h>
#include <math.h>
#include <cstdint>

#define N_NODES 100000
#define N_EDGES 3200000
#define F_IN    512
#define F_H     256
#define F_OUT   64

// ---------------- scratch (device globals: no alloc allowed) ----------------
__device__ int   g_deg[N_NODES];
__device__ int   g_cursor[N_NODES];
__device__ int   g_rowptr[N_NODES + 1];
__device__ float g_dis[N_NODES];
__device__ int   g_csr[N_EDGES];
__device__ float g_csrw[N_EDGES];       // per-edge weight dis[src]
__device__ int   g_blksum[128];
__device__ int   g_blkoff[128];
__device__ __nv_bfloat16 g_ahi[(size_t)N_NODES * F_IN];   // activation hi plane
__device__ __nv_bfloat16 g_alo[(size_t)N_NODES * F_IN];   // activation lo plane
__device__ float g_gout[(size_t)N_NODES * F_H];           // GEMM output (pre-agg) fp32
__device__ __nv_bfloat16 g_whi[4][(size_t)F_IN * F_H];    // W^T hi plane [N][K]
__device__ __nv_bfloat16 g_wlo[4][(size_t)F_IN * F_H];    // W^T lo plane [N][K]

// ---------------- packing helpers ----------------
__device__ __forceinline__ void split_bf16(float v, __nv_bfloat16& hi, __nv_bfloat16& lo) {
    hi = __float2bfloat16(v);
    lo = __float2bfloat16(v - __bfloat162float(hi));
}

__global__ void pack_x_kernel(const float* __restrict__ x,
                              __nv_bfloat16* __restrict__ hi,
                              __nv_bfloat16* __restrict__ lo, int n4) {
    int i = blockIdx.x * blockDim.x + threadIdx.x;
    if (i < n4) {
        float4 v = *(const float4*)(x + (size_t)i * 4);
        __nv_bfloat16 h0, l0, h1, l1, h2, l2, h3, l3;
        split_bf16(v.x, h0, l0); split_bf16(v.y, h1, l1);
        split_bf16(v.z, h2, l2); split_bf16(v.w, h3, l3);
        __nv_bfloat162 hh0 = __halves2bfloat162(h0, h1);
        __nv_bfloat162 hh1 = __halves2bfloat162(h2, h3);
        __nv_bfloat162 ll0 = __halves2bfloat162(l0, l1);
        __nv_bfloat162 ll1 = __halves2bfloat162(l2, l3);
        *(uint2*)(hi + (size_t)i * 4) = make_uint2(*(uint32_t*)&hh0, *(uint32_t*)&hh1);
        *(uint2*)(lo + (size_t)i * 4) = make_uint2(*(uint32_t*)&ll0, *(uint32_t*)&ll1);
    }
}

// W [K,N] fp32 -> W^T planes [N][K]
__global__ void pack_w_kernel(const float* __restrict__ W,
                              __nv_bfloat16* __restrict__ hi,
                              __nv_bfloat16* __restrict__ lo, int K, int N) {
    int i = blockIdx.x * blockDim.x + threadIdx.x;
    if (i < K * N) {
        int k = i / N, n = i % N;
        __nv_bfloat16 h, l;
        split_bf16(W[i], h, l);
        hi[(size_t)n * K + k] = h;
        lo[(size_t)n * K + k] = l;
    }
}

// ---------------- CSR build ----------------
__global__ void zero_kernel() {
    int i = blockIdx.x * blockDim.x + threadIdx.x;
    if (i < N_NODES) { g_deg[i] = 0; g_cursor[i] = 0; }
}
__global__ void count_kernel(const int* __restrict__ ei) {
    int e = blockIdx.x * blockDim.x + threadIdx.x;
    if (e < N_EDGES) atomicAdd(&g_deg[ei[N_EDGES + e]], 1);
}
__global__ void dis_kernel() {
    int n = blockIdx.x * blockDim.x + threadIdx.x;
    if (n < N_NODES) g_dis[n] = rsqrtf((float)g_deg[n] + 1.0f);
}
__global__ void scan1_kernel() {
    __shared__ int sh[1024];
    int tid = threadIdx.x;
    int idx = blockIdx.x * 1024 + tid;
    int v = (idx < N_NODES) ? g_deg[idx] : 0;
    sh[tid] = v;
    __syncthreads();
    #pragma unroll
    for (int off = 1; off < 1024; off <<= 1) {
        int t = (tid >= off) ? sh[tid - off] : 0;
        __syncthreads();
        sh[tid] += t;
        __syncthreads();
    }
    if (idx < N_NODES) g_rowptr[idx] = sh[tid] - v;
    if (tid == 1023) g_blksum[blockIdx.x] = sh[1023];
}
__global__ void scan2_kernel(int nblk) {
    if (threadIdx.x == 0) {
        int run = 0;
        for (int b = 0; b < nblk; b++) { int t = g_blksum[b]; g_blkoff[b] = run; run += t; }
        g_rowptr[N_NODES] = run;
    }
}
__global__ void scan3_kernel() {
    int idx = blockIdx.x * 1024 + threadIdx.x;
    if (idx < N_NODES) g_rowptr[idx] += g_blkoff[blockIdx.x];
}
__global__ void scatter_kernel(const int* __restrict__ ei) {
    int e = blockIdx.x * blockDim.x + threadIdx.x;
    if (e < N_EDGES) {
        int d = ei[N_EDGES + e];
        int s = ei[e];
        int pos = atomicAdd(&g_cursor[d], 1);
        int slot = g_rowptr[d] + pos;
        g_csr[slot] = s;
        g_csrw[slot] = g_dis[s];
    }
}

// ---------------- mma.sync bf16 GEMM: C[M,N] = A[M,K] @ W[K,N] (W^T planes given) ----------------
// fp32 emulation: C = Ah*Bh + Ah*Bl + Al*Bh (bf16 hi/lo planes). BM=128 BN=64 BK=32.
// 8 warps: 4 in M x 2 in N, warp tile 32x32. cp.async double-buffered, ldmatrix fragments.
#define RS 20  /* smem row stride in u32 = 80 bytes */
__device__ __forceinline__ void cp_async16(uint32_t dst, const void* src, int szr) {
    asm volatile("cp.async.ca.shared.global [%0], [%1], 16, %2;"
                 :: "r"(dst), "l"(src), "r"(szr));
}
__device__ __forceinline__ void mma16816(float* c, const uint32_t* a, const uint32_t* b) {
    asm volatile(
        "mma.sync.aligned.m16n8k16.row.col.f32.bf16.bf16.f32 "
        "{%0,%1,%2,%3}, {%4,%5,%6,%7}, {%8,%9}, {%0,%1,%2,%3};"
        : "+f"(c[0]), "+f"(c[1]), "+f"(c[2]), "+f"(c[3])
        : "r"(a[0]), "r"(a[1]), "r"(a[2]), "r"(a[3]), "r"(b[0]), "r"(b[1]));
}
__device__ __forceinline__ void ldsm_x4(uint32_t* r, uint32_t addr) {
    asm volatile("ldmatrix.sync.aligned.m8n8.x4.shared.b16 {%0,%1,%2,%3}, [%4];"
        : "=r"(r[0]), "=r"(r[1]), "=r"(r[2]), "=r"(r[3]) : "r"(addr));
}
__device__ __forceinline__ void ldsm_x2(uint32_t* r, uint32_t addr) {
    asm volatile("ldmatrix.sync.aligned.m8n8.x2.shared.b16 {%0,%1}, [%2];"
        : "=r"(r[0]), "=r"(r[1]) : "r"(addr));
}

__global__ void __launch_bounds__(256)
mma_gemm_kernel(const __nv_bfloat16* __restrict__ Ahi, const __nv_bfloat16* __restrict__ Alo,
                const __nv_bfloat16* __restrict__ Bhi, const __nv_bfloat16* __restrict__ Blo,
                float* __restrict__ C, int M, int N, int K) {
    extern __shared__ char smem[];
    // per buffer: A_hi [0,10240) A_lo [10240,20480) B_hi [20480,25600) B_lo [25600,30720)
    const int BUF = 30720;
    uint32_t sbase;
    asm("{ .reg .u64 t; cvta.to.shared.u64 t, %1; cvt.u32.u64 %0, t; }"
        : "=r"(sbase) : "l"(smem));

    int tid = threadIdx.x, lane = tid & 31, wid = tid >> 5;
    int gID = lane >> 2, tig = lane & 3;
    int warpM = (wid & 3) * 32, warpN = (wid >> 2) * 32;
    int bm = blockIdx.y * 128, bn = blockIdx.x * 64;

    // ldmatrix per-lane address offsets (within a plane, byte units)
    // A x4: rows (lane&7) + ((lane>>3)&1)*8, k-halves (lane>>4)*16B
    uint32_t aOff = (uint32_t)((warpM + (lane & 7) + ((lane >> 3) & 1) * 8) * 80
                               + (lane >> 4) * 16);
    // B x2: lanes 0-15 used; rows n = (lane&7), k-half ((lane>>3)&1)*16B
    int lb = lane & 15;
    uint32_t bOff = (uint32_t)((warpN + (lb & 7)) * 80 + ((lb >> 3) & 1) * 16);

    float acc[2][4][4];
    #pragma unroll
    for (int i = 0; i < 2; i++)
        #pragma unroll
        for (int j = 0; j < 4; j++)
            #pragma unroll
            for (int q = 0; q < 4; q++) acc[i][j][q] = 0.f;

    int nch = K >> 5;

    auto load_tile = [&](int buf, int c) {
        uint32_t bb = sbase + buf * BUF;
        #pragma unroll
        for (int it = 0; it < 4; it++) {
            int idx = tid + it * 256;
            int ch = idx & 3, r = (idx >> 2) & 127, pl = idx >> 9;
            int row = bm + r;
            int szr = (row < M) ? 16 : 0;
            int rowc = (row < M) ? row : (M - 1);
            const __nv_bfloat16* src = (pl ? Alo : Ahi) + (size_t)rowc * K + c * 32 + ch * 8;
            cp_async16(bb + pl * 10240 + r * 80 + ch * 16, src, szr);
        }
        #pragma unroll
        for (int it = 0; it < 2; it++) {
            int idx = tid + it * 256;
            int ch = idx & 3, r = (idx >> 2) & 63, pl = idx >> 8;
            const __nv_bfloat16* src = (pl ? Blo : Bhi) + (size_t)(bn + r) * K + c * 32 + ch * 8;
            cp_async16(bb + 20480 + pl * 5120 + r * 80 + ch * 16, src, 16);
        }
    };

    load_tile(0, 0);
    asm volatile("cp.async.commit_group;");

    for (int c = 0; c < nch; c++) {
        if (c + 1 < nch) load_tile((c + 1) & 1, c + 1);
        asm volatile("cp.async.commit_group;");
        asm volatile("cp.async.wait_group 1;");
        __syncthreads();

        uint32_t bufb = sbase + (c & 1) * BUF;
        uint32_t aHi = bufb + aOff;            // A hi plane base for this lane
        uint32_t aLo = aHi + 10240;
        uint32_t bHi = bufb + 20480 + bOff;
        uint32_t bLo = bHi + 5120;

        #pragma unroll
        for (int ks = 0; ks < 2; ks++) {
            uint32_t ah[2][4], al[2][4], bh[4][2], bl[4][2];
            #pragma unroll
            for (int mt = 0; mt < 2; mt++) {
                ldsm_x4(ah[mt], aHi + mt * (16 * 80) + ks * 32);
                ldsm_x4(al[mt], aLo + mt * (16 * 80) + ks * 32);
            }
            #pragma unroll
            for (int nt = 0; nt < 4; nt++) {
                ldsm_x2(bh[nt], bHi + nt * (8 * 80) + ks * 32);
                ldsm_x2(bl[nt], bLo + nt * (8 * 80) + ks * 32);
            }
            #pragma unroll
            for (int mt = 0; mt < 2; mt++)
                #pragma unroll
                for (int nt = 0; nt < 4; nt++) {
                    mma16816(acc[mt][nt], ah[mt], bh[nt]);
                    mma16816(acc[mt][nt], ah[mt], bl[nt]);
                    mma16816(acc[mt][nt], al[mt], bh[nt]);
                }
        }
        __syncthreads();
    }

    // epilogue: direct register -> global
    #pragma unroll
    for (int mt = 0; mt < 2; mt++) {
        int row0 = bm + warpM + mt * 16 + gID;
        #pragma unroll
        for (int nt = 0; nt < 4; nt++) {
            int col = bn + warpN + nt * 8 + tig * 2;
            if (row0 < M)
                *(float2*)(C + (size_t)row0 * N + col) = make_float2(acc[mt][nt][0], acc[mt][nt][1]);
            if (row0 + 8 < M)
                *(float2*)(C + (size_t)(row0 + 8) * N + col) = make_float2(acc[mt][nt][2], acc[mt][nt][3]);
        }
    }
}

// ---------------- aggregation with smem-staged edges ----------------
template<int F>
__global__ void agg_pack_kernel(const float* __restrict__ h,
                                const float* __restrict__ bias,
                                __nv_bfloat16* __restrict__ ohi,
                                __nv_bfloat16* __restrict__ olo) {
    __shared__ int   sE[128];
    __shared__ float sW[128];
    int node = blockIdx.x;
    int f = threadIdx.x;
    int beg = g_rowptr[node], end = g_rowptr[node + 1];
    float acc = 0.f;
    for (int cs = beg; cs < end; cs += 128) {
        int cnt = min(128, end - cs);
        if (f < cnt) { sE[f] = g_csr[cs + f]; sW[f] = g_csrw[cs + f]; }
        __syncthreads();
        #pragma unroll 4
        for (int i = 0; i < cnt; i++)
            acc = fmaf(sW[i], __ldg(&h[(size_t)sE[i] * F + f]), acc);
        __syncthreads();
    }
    float dn = g_dis[node];
    float v = dn * fmaf(dn, h[(size_t)node * F + f], acc) + bias[f];
    v = v > 0.f ? v : 0.01f * v;
    __nv_bfloat16 hi, lo;
    split_bf16(v, hi, lo);
    ohi[(size_t)node * F + f] = hi;
    olo[(size_t)node * F + f] = lo;
}

// last layer: agg (F=64) fused with bias + softmax. 4 nodes per 256-thread block.
__global__ void agg_softmax_kernel(const float* __restrict__ h,
                                   const float* __restrict__ bias,
                                   float* __restrict__ out) {
    __shared__ float sh[256];
    int g = threadIdx.x / 64;
    int f = threadIdx.x % 64;
    int node = blockIdx.x * 4 + g;
    bool valid = node < N_NODES;

    float v = 0.f;
    if (valid) {
        int beg = g_rowptr[node], end = g_rowptr[node + 1];
        float acc = 0.f;
        for (int e = beg; e < end; e++) {
            acc = fmaf(g_csrw[e], __ldg(&h[(size_t)g_csr[e] * 64 + f]), acc);
        }
        float dn = g_dis[node];
        v = dn * fmaf(dn, h[(size_t)node * 64 + f], acc) + bias[f];
    }
    sh[threadIdx.x] = valid ? v : -1e30f;
    __syncthreads();
    #pragma unroll
    for (int off = 32; off > 0; off >>= 1) {
        if (f < off) sh[threadIdx.x] = fmaxf(sh[threadIdx.x], sh[threadIdx.x + off]);
        __syncthreads();
    }
    float m = sh[g * 64];
    __syncthreads();
    float e = valid ? expf(v - m) : 0.f;
    sh[threadIdx.x] = e;
    __syncthreads();
    #pragma unroll
    for (int off = 32; off > 0; off >>= 1) {
        if (f < off) sh[threadIdx.x] += sh[threadIdx.x + off];
        __syncthreads();
    }
    float s = sh[g * 64];
    if (valid) out[(size_t)node * 64 + f] = e / s;
}

// ---------------- launch ----------------
extern "C" void kernel_launch(void* const* d_in, const int* in_sizes, int n_in,
                              void* d_out, int out_size) {
    const float* x  = (const float*)d_in[0];
    const int*   ei = (const int*)  d_in[1];
    const float* W0 = (const float*)d_in[2];
    const float* b0 = (const float*)d_in[3];
    const float* W1 = (const float*)d_in[4];
    const float* b1 = (const float*)d_in[5];
    const float* W2 = (const float*)d_in[6];
    const float* b2 = (const float*)d_in[7];
    const float* W3 = (const float*)d_in[8];
    const float* b3 = (const float*)d_in[9];
    float* out = (float*)d_out;

    __nv_bfloat16 *ahi, *alo, *whibase, *wlobase;
    float* gout;
    cudaGetSymbolAddress((void**)&ahi, g_ahi);
    cudaGetSymbolAddress((void**)&alo, g_alo);
    cudaGetSymbolAddress((void**)&whibase, g_whi);
    cudaGetSymbolAddress((void**)&wlobase, g_wlo);
    cudaGetSymbolAddress((void**)&gout, g_gout);
    const size_t WSTRIDE = (size_t)F_IN * F_H;

    cudaFuncSetAttribute(mma_gemm_kernel, cudaFuncAttributeMaxDynamicSharedMemorySize, 61440);

    const int TB = 256;
    int nblk_nodes = (N_NODES + TB - 1) / TB;
    int nblk_edges = (N_EDGES + TB - 1) / TB;
    int scan_blks = (N_NODES + 1023) / 1024;
    int mtiles = (N_NODES + 127) / 128;

    // packs first, then gemm0 (6th launch -> ncu window), then CSR build (needed before agg0)
    pack_x_kernel<<<(N_NODES * F_IN / 4 + TB - 1) / TB, TB>>>(x, ahi, alo, N_NODES * F_IN / 4);
    pack_w_kernel<<<(F_IN * F_H + TB - 1) / TB, TB>>>(W0, whibase, wlobase, F_IN, F_H);
    pack_w_kernel<<<(F_H * F_H + TB - 1) / TB, TB>>>(W1, whibase + WSTRIDE, wlobase + WSTRIDE, F_H, F_H);
    pack_w_kernel<<<(F_H * F_H + TB - 1) / TB, TB>>>(W2, whibase + 2 * WSTRIDE, wlobase + 2 * WSTRIDE, F_H, F_H);
    pack_w_kernel<<<(F_H * F_OUT + TB - 1) / TB, TB>>>(W3, whibase + 3 * WSTRIDE, wlobase + 3 * WSTRIDE, F_H, F_OUT);

    // Layer 0 GEMM: 512 -> 256
    mma_gemm_kernel<<<dim3(4, mtiles), TB, 61440>>>(ahi, alo, whibase, wlobase, gout,
                                                    N_NODES, F_H, F_IN);

    // CSR build (independent of GEMM; must precede agg)
    zero_kernel<<<nblk_nodes, TB>>>();
    count_kernel<<<nblk_edges, TB>>>(ei);
    dis_kernel<<<nblk_nodes, TB>>>();
    scan1_kernel<<<scan_blks, 1024>>>();
    scan2_kernel<<<1, 32>>>(scan_blks);
    scan3_kernel<<<scan_blks, 1024>>>();
    scatter_kernel<<<nblk_edges, TB>>>(ei);

    agg_pack_kernel<F_H><<<N_NODES, F_H>>>(gout, b0, ahi, alo);
    // Layer 1
    mma_gemm_kernel<<<dim3(4, mtiles), TB, 61440>>>(ahi, alo, whibase + WSTRIDE, wlobase + WSTRIDE,
                                                    gout, N_NODES, F_H, F_H);
    agg_pack_kernel<F_H><<<N_NODES, F_H>>>(gout, b1, ahi, alo);
    // Layer 2
    mma_gemm_kernel<<<dim3(4, mtiles), TB, 61440>>>(ahi, alo, whibase + 2 * WSTRIDE, wlobase + 2 * WSTRIDE,
                                                    gout, N_NODES, F_H, F_H);
    agg_pack_kernel<F_H><<<N_NODES, F_H>>>(gout, b2, ahi, alo);
    // Layer 3: 256 -> 64 + softmax
    mma_gemm_kernel<<<dim3(1, mtiles), TB, 61440>>>(ahi, alo, whibase + 3 * WSTRIDE, wlobase + 3 * WSTRIDE,
                                                    gout, N_NODES, F_OUT, F_H);
    agg_softmax_kernel<<<(N_NODES + 3) / 4, TB>>>(gout, b3, out);
}

// round 6
// speedup vs baseline: 2.0009x; 1.3608x over previous
#include <cuda_runtime.h>
#include <cuda_bf16.h>
#include <math.h>
#include <cstdint>

#define N_NODES 100000
#define N_EDGES 3200000
#define F_IN    512
#define F_H     256
#define F_OUT   64

// ---------------- scratch (device globals: no alloc allowed) ----------------
__device__ int   g_deg[N_NODES];
__device__ int   g_cursor[N_NODES];
__device__ int   g_rowptr[N_NODES + 1];
__device__ float g_dis[N_NODES];
__device__ int   g_csr[N_EDGES];
__device__ float g_csrw[N_EDGES];       // per-edge weight dis[src]
__device__ int   g_blksum[128];
__device__ int   g_blkoff[128];
__device__ __nv_bfloat16 g_ahi[(size_t)N_NODES * F_IN];   // activation hi plane
__device__ __nv_bfloat16 g_alo[(size_t)N_NODES * F_IN];   // activation lo plane
__device__ float g_gout[(size_t)N_NODES * F_H];           // GEMM output (pre-agg) fp32
__device__ __nv_bfloat16 g_whi[4][(size_t)F_IN * F_H];    // W^T hi plane [N][K]
__device__ __nv_bfloat16 g_wlo[4][(size_t)F_IN * F_H];    // W^T lo plane [N][K]

// ---------------- packing helpers ----------------
__device__ __forceinline__ void split_bf16(float v, __nv_bfloat16& hi, __nv_bfloat16& lo) {
    hi = __float2bfloat16(v);
    lo = __float2bfloat16(v - __bfloat162float(hi));
}

__global__ void pack_x_kernel(const float* __restrict__ x,
                              __nv_bfloat16* __restrict__ hi,
                              __nv_bfloat16* __restrict__ lo, int n4) {
    int i = blockIdx.x * blockDim.x + threadIdx.x;
    if (i < n4) {
        float4 v = *(const float4*)(x + (size_t)i * 4);
        __nv_bfloat16 h0, l0, h1, l1, h2, l2, h3, l3;
        split_bf16(v.x, h0, l0); split_bf16(v.y, h1, l1);
        split_bf16(v.z, h2, l2); split_bf16(v.w, h3, l3);
        __nv_bfloat162 hh0 = __halves2bfloat162(h0, h1);
        __nv_bfloat162 hh1 = __halves2bfloat162(h2, h3);
        __nv_bfloat162 ll0 = __halves2bfloat162(l0, l1);
        __nv_bfloat162 ll1 = __halves2bfloat162(l2, l3);
        *(uint2*)(hi + (size_t)i * 4) = make_uint2(*(uint32_t*)&hh0, *(uint32_t*)&hh1);
        *(uint2*)(lo + (size_t)i * 4) = make_uint2(*(uint32_t*)&ll0, *(uint32_t*)&ll1);
    }
}

// W [K,N] fp32 -> W^T planes [N][K]
__global__ void pack_w_kernel(const float* __restrict__ W,
                              __nv_bfloat16* __restrict__ hi,
                              __nv_bfloat16* __restrict__ lo, int K, int N) {
    int i = blockIdx.x * blockDim.x + threadIdx.x;
    if (i < K * N) {
        int k = i / N, n = i % N;
        __nv_bfloat16 h, l;
        split_bf16(W[i], h, l);
        hi[(size_t)n * K + k] = h;
        lo[(size_t)n * K + k] = l;
    }
}

// ---------------- CSR build ----------------
__global__ void zero_kernel() {
    int i = blockIdx.x * blockDim.x + threadIdx.x;
    if (i < N_NODES) { g_deg[i] = 0; g_cursor[i] = 0; }
}
__global__ void count_kernel(const int* __restrict__ ei) {
    int e = blockIdx.x * blockDim.x + threadIdx.x;
    if (e < N_EDGES) atomicAdd(&g_deg[ei[N_EDGES + e]], 1);
}
__global__ void dis_kernel() {
    int n = blockIdx.x * blockDim.x + threadIdx.x;
    if (n < N_NODES) g_dis[n] = rsqrtf((float)g_deg[n] + 1.0f);
}
__global__ void scan1_kernel() {
    __shared__ int sh[1024];
    int tid = threadIdx.x;
    int idx = blockIdx.x * 1024 + tid;
    int v = (idx < N_NODES) ? g_deg[idx] : 0;
    sh[tid] = v;
    __syncthreads();
    #pragma unroll
    for (int off = 1; off < 1024; off <<= 1) {
        int t = (tid >= off) ? sh[tid - off] : 0;
        __syncthreads();
        sh[tid] += t;
        __syncthreads();
    }
    if (idx < N_NODES) g_rowptr[idx] = sh[tid] - v;
    if (tid == 1023) g_blksum[blockIdx.x] = sh[1023];
}
__global__ void scan2_kernel(int nblk) {
    if (threadIdx.x == 0) {
        int run = 0;
        for (int b = 0; b < nblk; b++) { int t = g_blksum[b]; g_blkoff[b] = run; run += t; }
        g_rowptr[N_NODES] = run;
    }
}
__global__ void scan3_kernel() {
    int idx = blockIdx.x * 1024 + threadIdx.x;
    if (idx < N_NODES) g_rowptr[idx] += g_blkoff[blockIdx.x];
}
__global__ void scatter_kernel(const int* __restrict__ ei) {
    int e = blockIdx.x * blockDim.x + threadIdx.x;
    if (e < N_EDGES) {
        int d = ei[N_EDGES + e];
        int s = ei[e];
        int pos = atomicAdd(&g_cursor[d], 1);
        int slot = g_rowptr[d] + pos;
        g_csr[slot] = s;
        g_csrw[slot] = g_dis[s];
    }
}

// ---------------- mma.sync bf16 GEMM: C[M,N] = A[M,K] @ W[K,N] (W^T planes given) ----------------
// fp32 emulation: C = Ah*Bh + Ah*Bl + Al*Bh. BM=128, BN template, BK=32.
// 8 warps: 4 in M x 2 in N, warp tile 32 x (BN/2). cp.async double-buffered, ldmatrix fragments.
#define RS 20  /* smem row stride in u32 = 80 bytes */
__device__ __forceinline__ void cp_async16(uint32_t dst, const void* src, int szr) {
    asm volatile("cp.async.ca.shared.global [%0], [%1], 16, %2;"
                 :: "r"(dst), "l"(src), "r"(szr));
}
__device__ __forceinline__ void mma16816(float* c, const uint32_t* a, const uint32_t* b) {
    asm volatile(
        "mma.sync.aligned.m16n8k16.row.col.f32.bf16.bf16.f32 "
        "{%0,%1,%2,%3}, {%4,%5,%6,%7}, {%8,%9}, {%0,%1,%2,%3};"
        : "+f"(c[0]), "+f"(c[1]), "+f"(c[2]), "+f"(c[3])
        : "r"(a[0]), "r"(a[1]), "r"(a[2]), "r"(a[3]), "r"(b[0]), "r"(b[1]));
}
__device__ __forceinline__ void ldsm_x4(uint32_t* r, uint32_t addr) {
    asm volatile("ldmatrix.sync.aligned.m8n8.x4.shared.b16 {%0,%1,%2,%3}, [%4];"
        : "=r"(r[0]), "=r"(r[1]), "=r"(r[2]), "=r"(r[3]) : "r"(addr));
}
__device__ __forceinline__ void ldsm_x2(uint32_t* r, uint32_t addr) {
    asm volatile("ldmatrix.sync.aligned.m8n8.x2.shared.b16 {%0,%1}, [%2];"
        : "=r"(r[0]), "=r"(r[1]) : "r"(addr));
}

template<int BN>
__global__ void __launch_bounds__(256)
mma_gemm_kernel(const __nv_bfloat16* __restrict__ Ahi, const __nv_bfloat16* __restrict__ Alo,
                const __nv_bfloat16* __restrict__ Bhi, const __nv_bfloat16* __restrict__ Blo,
                float* __restrict__ C, int M, int N, int K) {
    extern __shared__ char smem[];
    // per buffer: A_hi [0,10240) A_lo [10240,20480) B_hi [20480,+BN*80) B_lo follows
    const int BSZ = BN * 80;
    const int BUF = 20480 + 2 * BSZ;
    const int NT = BN / 16;               // n8 tiles per warp (warp covers BN/2 cols)
    uint32_t sbase;
    asm("{ .reg .u64 t; cvta.to.shared.u64 t, %1; cvt.u32.u64 %0, t; }"
        : "=r"(sbase) : "l"(smem));

    int tid = threadIdx.x, lane = tid & 31, wid = tid >> 5;
    int gID = lane >> 2, tig = lane & 3;
    int warpM = (wid & 3) * 32, warpN = (wid >> 2) * (BN / 2);
    int bm = blockIdx.y * 128, bn = blockIdx.x * BN;

    uint32_t aOff = (uint32_t)((warpM + (lane & 7) + ((lane >> 3) & 1) * 8) * 80
                               + (lane >> 4) * 16);
    int lb = lane & 15;
    uint32_t bOff = (uint32_t)((warpN + (lb & 7)) * 80 + ((lb >> 3) & 1) * 16);

    float acc[2][NT][4];
    #pragma unroll
    for (int i = 0; i < 2; i++)
        #pragma unroll
        for (int j = 0; j < NT; j++)
            #pragma unroll
            for (int q = 0; q < 4; q++) acc[i][j][q] = 0.f;

    int nch = K >> 5;

    auto load_tile = [&](int buf, int c) {
        uint32_t bb = sbase + buf * BUF;
        #pragma unroll
        for (int it = 0; it < 4; it++) {
            int idx = tid + it * 256;
            int ch = idx & 3, r = (idx >> 2) & 127, pl = idx >> 9;
            int row = bm + r;
            int szr = (row < M) ? 16 : 0;
            int rowc = (row < M) ? row : (M - 1);
            const __nv_bfloat16* src = (pl ? Alo : Ahi) + (size_t)rowc * K + c * 32 + ch * 8;
            cp_async16(bb + pl * 10240 + r * 80 + ch * 16, src, szr);
        }
        #pragma unroll
        for (int it = 0; it < BN / 32; it++) {
            int idx = tid + it * 256;
            int ch = idx & 3, r = (idx >> 2) % BN, pl = idx / (BN * 4);
            const __nv_bfloat16* src = (pl ? Blo : Bhi) + (size_t)(bn + r) * K + c * 32 + ch * 8;
            cp_async16(bb + 20480 + pl * BSZ + r * 80 + ch * 16, src, 16);
        }
    };

    load_tile(0, 0);
    asm volatile("cp.async.commit_group;");

    for (int c = 0; c < nch; c++) {
        if (c + 1 < nch) load_tile((c + 1) & 1, c + 1);
        asm volatile("cp.async.commit_group;");
        asm volatile("cp.async.wait_group 1;");
        __syncthreads();

        uint32_t bufb = sbase + (c & 1) * BUF;
        uint32_t aHi = bufb + aOff;
        uint32_t aLo = aHi + 10240;
        uint32_t bHi = bufb + 20480 + bOff;
        uint32_t bLo = bHi + BSZ;

        #pragma unroll
        for (int ks = 0; ks < 2; ks++) {
            uint32_t ah[2][4], al[2][4], bh[NT][2], bl[NT][2];
            #pragma unroll
            for (int mt = 0; mt < 2; mt++) {
                ldsm_x4(ah[mt], aHi + mt * (16 * 80) + ks * 32);
                ldsm_x4(al[mt], aLo + mt * (16 * 80) + ks * 32);
            }
            #pragma unroll
            for (int nt = 0; nt < NT; nt++) {
                ldsm_x2(bh[nt], bHi + nt * (8 * 80) + ks * 32);
                ldsm_x2(bl[nt], bLo + nt * (8 * 80) + ks * 32);
            }
            #pragma unroll
            for (int mt = 0; mt < 2; mt++)
                #pragma unroll
                for (int nt = 0; nt < NT; nt++) {
                    mma16816(acc[mt][nt], ah[mt], bh[nt]);
                    mma16816(acc[mt][nt], ah[mt], bl[nt]);
                    mma16816(acc[mt][nt], al[mt], bh[nt]);
                }
        }
        __syncthreads();
    }

    // epilogue: direct register -> global
    #pragma unroll
    for (int mt = 0; mt < 2; mt++) {
        int row0 = bm + warpM + mt * 16 + gID;
        #pragma unroll
        for (int nt = 0; nt < NT; nt++) {
            int col = bn + warpN + nt * 8 + tig * 2;
            if (row0 < M)
                *(float2*)(C + (size_t)row0 * N + col) = make_float2(acc[mt][nt][0], acc[mt][nt][1]);
            if (row0 + 8 < M)
                *(float2*)(C + (size_t)(row0 + 8) * N + col) = make_float2(acc[mt][nt][2], acc[mt][nt][3]);
        }
    }
}

// ---------------- aggregation: float4 gather, 4 nodes per 256-thread block ----------------
// group = 64 threads per node, thread handles features [4t, 4t+4)
__global__ void __launch_bounds__(256)
agg_pack_kernel(const float* __restrict__ h,
                const float* __restrict__ bias,
                __nv_bfloat16* __restrict__ ohi,
                __nv_bfloat16* __restrict__ olo) {
    __shared__ int   sE[4][64];
    __shared__ float sW[4][64];
    int g = threadIdx.x >> 6;      // node group 0..3
    int t = threadIdx.x & 63;      // thread in group
    int node = blockIdx.x * 4 + g;
    bool valid = node < N_NODES;

    int beg = 0, end = 0;
    if (valid) { beg = g_rowptr[node]; end = g_rowptr[node + 1]; }
    float4 acc = make_float4(0.f, 0.f, 0.f, 0.f);

    for (int cs = beg; cs < end; cs += 64) {
        int cnt = min(64, end - cs);
        if (t < cnt) { sE[g][t] = g_csr[cs + t]; sW[g][t] = g_csrw[cs + t]; }
        __syncwarp();   // group spans 2 warps; need group-wide sync:
        __syncthreads();
        #pragma unroll 2
        for (int i = 0; i < cnt; i++) {
            float w = sW[g][i];
            float4 v = __ldg((const float4*)(h + (size_t)sE[g][i] * F_H + t * 4));
            acc.x = fmaf(w, v.x, acc.x); acc.y = fmaf(w, v.y, acc.y);
            acc.z = fmaf(w, v.z, acc.z); acc.w = fmaf(w, v.w, acc.w);
        }
        __syncthreads();
    }
    if (valid) {
        float dn = g_dis[node];
        float4 hv = *(const float4*)(h + (size_t)node * F_H + t * 4);
        const float4 bv = *(const float4*)(bias + t * 4);
        float r[4] = {
            dn * fmaf(dn, hv.x, acc.x) + bv.x,
            dn * fmaf(dn, hv.y, acc.y) + bv.y,
            dn * fmaf(dn, hv.z, acc.z) + bv.z,
            dn * fmaf(dn, hv.w, acc.w) + bv.w };
        __nv_bfloat16 hi[4], lo[4];
        #pragma unroll
        for (int q = 0; q < 4; q++) {
            float v = r[q] > 0.f ? r[q] : 0.01f * r[q];
            split_bf16(v, hi[q], lo[q]);
        }
        __nv_bfloat162 hh0 = __halves2bfloat162(hi[0], hi[1]);
        __nv_bfloat162 hh1 = __halves2bfloat162(hi[2], hi[3]);
        __nv_bfloat162 ll0 = __halves2bfloat162(lo[0], lo[1]);
        __nv_bfloat162 ll1 = __halves2bfloat162(lo[2], lo[3]);
        *(uint2*)(ohi + (size_t)node * F_H + t * 4) = make_uint2(*(uint32_t*)&hh0, *(uint32_t*)&hh1);
        *(uint2*)(olo + (size_t)node * F_H + t * 4) = make_uint2(*(uint32_t*)&ll0, *(uint32_t*)&ll1);
    }
}

// last layer: agg (F=64) + bias + softmax. 16 threads x float4 per node, 16 nodes per block.
__global__ void __launch_bounds__(256)
agg_softmax_kernel(const float* __restrict__ h,
                   const float* __restrict__ bias,
                   float* __restrict__ out) {
    int g = threadIdx.x >> 4;     // node group 0..15
    int t = threadIdx.x & 15;     // thread in group
    int node = blockIdx.x * 16 + g;
    bool valid = node < N_NODES;

    float4 acc = make_float4(0.f, 0.f, 0.f, 0.f);
    if (valid) {
        int beg = g_rowptr[node], end = g_rowptr[node + 1];
        for (int e = beg; e < end; e++) {
            float w = g_csrw[e];
            float4 v = __ldg((const float4*)(h + (size_t)g_csr[e] * 64 + t * 4));
            acc.x = fmaf(w, v.x, acc.x); acc.y = fmaf(w, v.y, acc.y);
            acc.z = fmaf(w, v.z, acc.z); acc.w = fmaf(w, v.w, acc.w);
        }
        float dn = g_dis[node];
        float4 hv = *(const float4*)(h + (size_t)node * 64 + t * 4);
        const float4 bv = *(const float4*)(bias + t * 4);
        acc.x = dn * fmaf(dn, hv.x, acc.x) + bv.x;
        acc.y = dn * fmaf(dn, hv.y, acc.y) + bv.y;
        acc.z = dn * fmaf(dn, hv.z, acc.z) + bv.z;
        acc.w = dn * fmaf(dn, hv.w, acc.w) + bv.w;
    }
    // softmax over 64 values spread across 16 lanes x 4 (within half-warp groups)
    float m = fmaxf(fmaxf(acc.x, acc.y), fmaxf(acc.z, acc.w));
    #pragma unroll
    for (int off = 8; off > 0; off >>= 1)
        m = fmaxf(m, __shfl_xor_sync(0xffffffffu, m, off, 16));
    float ex = expf(acc.x - m), ey = expf(acc.y - m);
    float ez = expf(acc.z - m), ew = expf(acc.w - m);
    float s = ex + ey + ez + ew;
    #pragma unroll
    for (int off = 8; off > 0; off >>= 1)
        s += __shfl_xor_sync(0xffffffffu, s, off, 16);
    if (valid) {
        float inv = 1.f / s;
        *(float4*)(out + (size_t)node * 64 + t * 4) = make_float4(ex * inv, ey * inv, ez * inv, ew * inv);
    }
}

// ---------------- launch ----------------
extern "C" void kernel_launch(void* const* d_in, const int* in_sizes, int n_in,
                              void* d_out, int out_size) {
    const float* x  = (const float*)d_in[0];
    const int*   ei = (const int*)  d_in[1];
    const float* W0 = (const float*)d_in[2];
    const float* b0 = (const float*)d_in[3];
    const float* W1 = (const float*)d_in[4];
    const float* b1 = (const float*)d_in[5];
    const float* W2 = (const float*)d_in[6];
    const float* b2 = (const float*)d_in[7];
    const float* W3 = (const float*)d_in[8];
    const float* b3 = (const float*)d_in[9];
    float* out = (float*)d_out;

    __nv_bfloat16 *ahi, *alo, *whibase, *wlobase;
    float* gout;
    cudaGetSymbolAddress((void**)&ahi, g_ahi);
    cudaGetSymbolAddress((void**)&alo, g_alo);
    cudaGetSymbolAddress((void**)&whibase, g_whi);
    cudaGetSymbolAddress((void**)&wlobase, g_wlo);
    cudaGetSymbolAddress((void**)&gout, g_gout);
    const size_t WSTRIDE = (size_t)F_IN * F_H;

    const int SM128 = 20480 + 2 * 128 * 80;          // per buffer
    const int SM64  = 20480 + 2 * 64 * 80;
    cudaFuncSetAttribute(mma_gemm_kernel<128>, cudaFuncAttributeMaxDynamicSharedMemorySize, 2 * SM128);
    cudaFuncSetAttribute(mma_gemm_kernel<64>,  cudaFuncAttributeMaxDynamicSharedMemorySize, 2 * SM64);

    const int TB = 256;
    int nblk_nodes = (N_NODES + TB - 1) / TB;
    int nblk_edges = (N_EDGES + TB - 1) / TB;
    int scan_blks = (N_NODES + 1023) / 1024;
    int mtiles = (N_NODES + 127) / 128;

    // launch order: gemm0 is the 4th launch (ncu capture window)
    pack_x_kernel<<<(N_NODES * F_IN / 4 + TB - 1) / TB, TB>>>(x, ahi, alo, N_NODES * F_IN / 4);
    pack_w_kernel<<<(F_IN * F_H + TB - 1) / TB, TB>>>(W0, whibase, wlobase, F_IN, F_H);
    pack_w_kernel<<<(F_H * F_H + TB - 1) / TB, TB>>>(W1, whibase + WSTRIDE, wlobase + WSTRIDE, F_H, F_H);

    // Layer 0 GEMM: 512 -> 256  (4th launch -> profiled)
    mma_gemm_kernel<128><<<dim3(2, mtiles), TB, 2 * SM128>>>(ahi, alo, whibase, wlobase, gout,
                                                             N_NODES, F_H, F_IN);

    pack_w_kernel<<<(F_H * F_H + TB - 1) / TB, TB>>>(W2, whibase + 2 * WSTRIDE, wlobase + 2 * WSTRIDE, F_H, F_H);
    pack_w_kernel<<<(F_H * F_OUT + TB - 1) / TB, TB>>>(W3, whibase + 3 * WSTRIDE, wlobase + 3 * WSTRIDE, F_H, F_OUT);

    // CSR build
    zero_kernel<<<nblk_nodes, TB>>>();
    count_kernel<<<nblk_edges, TB>>>(ei);
    dis_kernel<<<nblk_nodes, TB>>>();
    scan1_kernel<<<scan_blks, 1024>>>();
    scan2_kernel<<<1, 32>>>(scan_blks);
    scan3_kernel<<<scan_blks, 1024>>>();
    scatter_kernel<<<nblk_edges, TB>>>(ei);

    agg_pack_kernel<<<(N_NODES + 3) / 4, TB>>>(gout, b0, ahi, alo);
    // Layer 1
    mma_gemm_kernel<128><<<dim3(2, mtiles), TB, 2 * SM128>>>(ahi, alo, whibase + WSTRIDE, wlobase + WSTRIDE,
                                                             gout, N_NODES, F_H, F_H);
    agg_pack_kernel<<<(N_NODES + 3) / 4, TB>>>(gout, b1, ahi, alo);
    // Layer 2
    mma_gemm_kernel<128><<<dim3(2, mtiles), TB, 2 * SM128>>>(ahi, alo, whibase + 2 * WSTRIDE, wlobase + 2 * WSTRIDE,
                                                             gout, N_NODES, F_H, F_H);
    agg_pack_kernel<<<(N_NODES + 3) / 4, TB>>>(gout, b2, ahi, alo);
    // Layer 3: 256 -> 64 + softmax
    mma_gemm_kernel<64><<<dim3(1, mtiles), TB, 2 * SM64>>>(ahi, alo, whibase + 3 * WSTRIDE, wlobase + 3 * WSTRIDE,
                                                           gout, N_NODES, F_OUT, F_H);
    agg_softmax_kernel<<<(N_NODES + 15) / 16, TB>>>(gout, b3, out);
}

// round 7
// speedup vs baseline: 2.0650x; 1.0320x over previous
#include <cuda_runtime.h>
#include <cuda_bf16.h>
#include <math.h>
#include <cstdint>

#define N_NODES 100000
#define N_EDGES 3200000
#define F_IN    512
#define F_H     256
#define F_OUT   64

// ---------------- scratch (device globals: no alloc allowed) ----------------
__device__ int   g_deg[N_NODES];
__device__ int   g_cursor[N_NODES];
__device__ int   g_rowptr[N_NODES + 1];
__device__ float g_dis[N_NODES];
__device__ int   g_csr[N_EDGES];
__device__ float g_csrw[N_EDGES];       // per-edge weight dis[src]
__device__ int   g_blksum[128];
__device__ int   g_blkoff[128];
__device__ __nv_bfloat16 g_ahi[(size_t)N_NODES * F_IN];   // activation hi plane
__device__ __nv_bfloat16 g_alo[(size_t)N_NODES * F_IN];   // activation lo plane
__device__ float g_gout[(size_t)N_NODES * F_H];           // GEMM output (pre-agg) fp32
__device__ __nv_bfloat16 g_whi[4][(size_t)F_IN * F_H];    // W^T hi plane [N][K]
__device__ __nv_bfloat16 g_wlo[4][(size_t)F_IN * F_H];    // W^T lo plane [N][K]

// ---------------- packing helpers ----------------
__device__ __forceinline__ void split_bf16(float v, __nv_bfloat16& hi, __nv_bfloat16& lo) {
    hi = __float2bfloat16(v);
    lo = __float2bfloat16(v - __bfloat162float(hi));
}

__global__ void pack_x_kernel(const float* __restrict__ x,
                              __nv_bfloat16* __restrict__ hi,
                              __nv_bfloat16* __restrict__ lo, int n4) {
    int i = blockIdx.x * blockDim.x + threadIdx.x;
    if (i < n4) {
        float4 v = *(const float4*)(x + (size_t)i * 4);
        __nv_bfloat16 h0, l0, h1, l1, h2, l2, h3, l3;
        split_bf16(v.x, h0, l0); split_bf16(v.y, h1, l1);
        split_bf16(v.z, h2, l2); split_bf16(v.w, h3, l3);
        __nv_bfloat162 hh0 = __halves2bfloat162(h0, h1);
        __nv_bfloat162 hh1 = __halves2bfloat162(h2, h3);
        __nv_bfloat162 ll0 = __halves2bfloat162(l0, l1);
        __nv_bfloat162 ll1 = __halves2bfloat162(l2, l3);
        *(uint2*)(hi + (size_t)i * 4) = make_uint2(*(uint32_t*)&hh0, *(uint32_t*)&hh1);
        *(uint2*)(lo + (size_t)i * 4) = make_uint2(*(uint32_t*)&ll0, *(uint32_t*)&ll1);
    }
}

// W [K,N] fp32 -> W^T planes [N][K]
__global__ void pack_w_kernel(const float* __restrict__ W,
                              __nv_bfloat16* __restrict__ hi,
                              __nv_bfloat16* __restrict__ lo, int K, int N) {
    int i = blockIdx.x * blockDim.x + threadIdx.x;
    if (i < K * N) {
        int k = i / N, n = i % N;
        __nv_bfloat16 h, l;
        split_bf16(W[i], h, l);
        hi[(size_t)n * K + k] = h;
        lo[(size_t)n * K + k] = l;
    }
}

// ---------------- CSR build ----------------
__global__ void zero_kernel() {
    int i = blockIdx.x * blockDim.x + threadIdx.x;
    if (i < N_NODES) { g_deg[i] = 0; g_cursor[i] = 0; }
}
__global__ void count_kernel(const int* __restrict__ ei) {
    int e = blockIdx.x * blockDim.x + threadIdx.x;
    if (e < N_EDGES) atomicAdd(&g_deg[ei[N_EDGES + e]], 1);
}
__global__ void dis_kernel() {
    int n = blockIdx.x * blockDim.x + threadIdx.x;
    if (n < N_NODES) g_dis[n] = rsqrtf((float)g_deg[n] + 1.0f);
}
__global__ void scan1_kernel() {
    __shared__ int sh[1024];
    int tid = threadIdx.x;
    int idx = blockIdx.x * 1024 + tid;
    int v = (idx < N_NODES) ? g_deg[idx] : 0;
    sh[tid] = v;
    __syncthreads();
    #pragma unroll
    for (int off = 1; off < 1024; off <<= 1) {
        int t = (tid >= off) ? sh[tid - off] : 0;
        __syncthreads();
        sh[tid] += t;
        __syncthreads();
    }
    if (idx < N_NODES) g_rowptr[idx] = sh[tid] - v;
    if (tid == 1023) g_blksum[blockIdx.x] = sh[1023];
}
__global__ void scan2_kernel(int nblk) {
    if (threadIdx.x == 0) {
        int run = 0;
        for (int b = 0; b < nblk; b++) { int t = g_blksum[b]; g_blkoff[b] = run; run += t; }
        g_rowptr[N_NODES] = run;
    }
}
__global__ void scan3_kernel() {
    int idx = blockIdx.x * 1024 + threadIdx.x;
    if (idx < N_NODES) g_rowptr[idx] += g_blkoff[blockIdx.x];
}
__global__ void scatter_kernel(const int* __restrict__ ei) {
    int e = blockIdx.x * blockDim.x + threadIdx.x;
    if (e < N_EDGES) {
        int d = ei[N_EDGES + e];
        int s = ei[e];
        int pos = atomicAdd(&g_cursor[d], 1);
        int slot = g_rowptr[d] + pos;
        g_csr[slot] = s;
        g_csrw[slot] = g_dis[s];
    }
}

// ---------------- mma.sync bf16 GEMM: C[M,N] = A[M,K] @ W[K,N] (W^T planes given) ----------------
// fp32 emulation: C = Ah*Bh + Al*Bh + Ah*Bl. BM=128, BN template, BK=32.
// 8 warps: 4 in M x 2 in N, warp tile 32 x (BN/2). cp.async double-buffered, ldmatrix fragments.
// B hi/lo fragments share registers (two phases per k-step) -> <=128 regs -> 2 CTAs/SM.
__device__ __forceinline__ void cp_async16(uint32_t dst, const void* src, int szr) {
    asm volatile("cp.async.ca.shared.global [%0], [%1], 16, %2;"
                 :: "r"(dst), "l"(src), "r"(szr));
}
__device__ __forceinline__ void mma16816(float* c, const uint32_t* a, const uint32_t* b) {
    asm volatile(
        "mma.sync.aligned.m16n8k16.row.col.f32.bf16.bf16.f32 "
        "{%0,%1,%2,%3}, {%4,%5,%6,%7}, {%8,%9}, {%0,%1,%2,%3};"
        : "+f"(c[0]), "+f"(c[1]), "+f"(c[2]), "+f"(c[3])
        : "r"(a[0]), "r"(a[1]), "r"(a[2]), "r"(a[3]), "r"(b[0]), "r"(b[1]));
}
__device__ __forceinline__ void ldsm_x4(uint32_t* r, uint32_t addr) {
    asm volatile("ldmatrix.sync.aligned.m8n8.x4.shared.b16 {%0,%1,%2,%3}, [%4];"
        : "=r"(r[0]), "=r"(r[1]), "=r"(r[2]), "=r"(r[3]) : "r"(addr));
}
__device__ __forceinline__ void ldsm_x2(uint32_t* r, uint32_t addr) {
    asm volatile("ldmatrix.sync.aligned.m8n8.x2.shared.b16 {%0,%1}, [%2];"
        : "=r"(r[0]), "=r"(r[1]) : "r"(addr));
}

template<int BN>
__global__ void __launch_bounds__(256, 2)
mma_gemm_kernel(const __nv_bfloat16* __restrict__ Ahi, const __nv_bfloat16* __restrict__ Alo,
                const __nv_bfloat16* __restrict__ Bhi, const __nv_bfloat16* __restrict__ Blo,
                float* __restrict__ C, int M, int N, int K) {
    extern __shared__ char smem[];
    // per buffer: A_hi [0,10240) A_lo [10240,20480) B_hi [20480,+BN*80) B_lo follows
    const int BSZ = BN * 80;
    const int BUF = 20480 + 2 * BSZ;
    const int NT = BN / 16;               // n8 tiles per warp (warp covers BN/2 cols)
    uint32_t sbase;
    asm("{ .reg .u64 t; cvta.to.shared.u64 t, %1; cvt.u32.u64 %0, t; }"
        : "=r"(sbase) : "l"(smem));

    int tid = threadIdx.x, lane = tid & 31, wid = tid >> 5;
    int gID = lane >> 2, tig = lane & 3;
    int warpM = (wid & 3) * 32, warpN = (wid >> 2) * (BN / 2);
    int bm = blockIdx.y * 128, bn = blockIdx.x * BN;

    uint32_t aOff = (uint32_t)((warpM + (lane & 7) + ((lane >> 3) & 1) * 8) * 80
                               + (lane >> 4) * 16);
    int lb = lane & 15;
    uint32_t bOff = (uint32_t)((warpN + (lb & 7)) * 80 + ((lb >> 3) & 1) * 16);

    float acc[2][NT][4];
    #pragma unroll
    for (int i = 0; i < 2; i++)
        #pragma unroll
        for (int j = 0; j < NT; j++)
            #pragma unroll
            for (int q = 0; q < 4; q++) acc[i][j][q] = 0.f;

    int nch = K >> 5;

    auto load_tile = [&](int buf, int c) {
        uint32_t bb = sbase + buf * BUF;
        #pragma unroll
        for (int it = 0; it < 4; it++) {
            int idx = tid + it * 256;
            int ch = idx & 3, r = (idx >> 2) & 127, pl = idx >> 9;
            int row = bm + r;
            int szr = (row < M) ? 16 : 0;
            int rowc = (row < M) ? row : (M - 1);
            const __nv_bfloat16* src = (pl ? Alo : Ahi) + (size_t)rowc * K + c * 32 + ch * 8;
            cp_async16(bb + pl * 10240 + r * 80 + ch * 16, src, szr);
        }
        #pragma unroll
        for (int it = 0; it < BN / 32; it++) {
            int idx = tid + it * 256;
            int ch = idx & 3, r = (idx >> 2) % BN, pl = idx / (BN * 4);
            const __nv_bfloat16* src = (pl ? Blo : Bhi) + (size_t)(bn + r) * K + c * 32 + ch * 8;
            cp_async16(bb + 20480 + pl * BSZ + r * 80 + ch * 16, src, 16);
        }
    };

    load_tile(0, 0);
    asm volatile("cp.async.commit_group;");

    for (int c = 0; c < nch; c++) {
        if (c + 1 < nch) load_tile((c + 1) & 1, c + 1);
        asm volatile("cp.async.commit_group;");
        asm volatile("cp.async.wait_group 1;");
        __syncthreads();

        uint32_t bufb = sbase + (c & 1) * BUF;
        uint32_t aHi = bufb + aOff;
        uint32_t aLo = aHi + 10240;
        uint32_t bHi = bufb + 20480 + bOff;
        uint32_t bLo = bHi + BSZ;

        #pragma unroll
        for (int ks = 0; ks < 2; ks++) {
            uint32_t ah[2][4], al[2][4], bb2[NT][2];
            #pragma unroll
            for (int mt = 0; mt < 2; mt++) {
                ldsm_x4(ah[mt], aHi + mt * (16 * 80) + ks * 32);
                ldsm_x4(al[mt], aLo + mt * (16 * 80) + ks * 32);
            }
            // phase 1: B hi plane -> ah*bh + al*bh
            #pragma unroll
            for (int nt = 0; nt < NT; nt++)
                ldsm_x2(bb2[nt], bHi + nt * (8 * 80) + ks * 32);
            #pragma unroll
            for (int mt = 0; mt < 2; mt++)
                #pragma unroll
                for (int nt = 0; nt < NT; nt++) {
                    mma16816(acc[mt][nt], ah[mt], bb2[nt]);
                    mma16816(acc[mt][nt], al[mt], bb2[nt]);
                }
            // phase 2: B lo plane -> ah*bl (reuse bb2 registers)
            #pragma unroll
            for (int nt = 0; nt < NT; nt++)
                ldsm_x2(bb2[nt], bLo + nt * (8 * 80) + ks * 32);
            #pragma unroll
            for (int mt = 0; mt < 2; mt++)
                #pragma unroll
                for (int nt = 0; nt < NT; nt++)
                    mma16816(acc[mt][nt], ah[mt], bb2[nt]);
        }
        __syncthreads();
    }

    // epilogue: direct register -> global
    #pragma unroll
    for (int mt = 0; mt < 2; mt++) {
        int row0 = bm + warpM + mt * 16 + gID;
        #pragma unroll
        for (int nt = 0; nt < NT; nt++) {
            int col = bn + warpN + nt * 8 + tig * 2;
            if (row0 < M)
                *(float2*)(C + (size_t)row0 * N + col) = make_float2(acc[mt][nt][0], acc[mt][nt][1]);
            if (row0 + 8 < M)
                *(float2*)(C + (size_t)(row0 + 8) * N + col) = make_float2(acc[mt][nt][2], acc[mt][nt][3]);
        }
    }
}

// ---------------- aggregation: float4 gather, 4 nodes per 256-thread block ----------------
__global__ void __launch_bounds__(256)
agg_pack_kernel(const float* __restrict__ h,
                const float* __restrict__ bias,
                __nv_bfloat16* __restrict__ ohi,
                __nv_bfloat16* __restrict__ olo) {
    __shared__ int   sE[4][64];
    __shared__ float sW[4][64];
    int g = threadIdx.x >> 6;      // node group 0..3
    int t = threadIdx.x & 63;      // thread in group
    int node = blockIdx.x * 4 + g;
    bool valid = node < N_NODES;

    int beg = 0, end = 0;
    if (valid) { beg = g_rowptr[node]; end = g_rowptr[node + 1]; }
    float4 acc = make_float4(0.f, 0.f, 0.f, 0.f);

    for (int cs = beg; cs < end; cs += 64) {
        int cnt = min(64, end - cs);
        if (t < cnt) { sE[g][t] = g_csr[cs + t]; sW[g][t] = g_csrw[cs + t]; }
        __syncthreads();
        #pragma unroll 2
        for (int i = 0; i < cnt; i++) {
            float w = sW[g][i];
            float4 v = __ldg((const float4*)(h + (size_t)sE[g][i] * F_H + t * 4));
            acc.x = fmaf(w, v.x, acc.x); acc.y = fmaf(w, v.y, acc.y);
            acc.z = fmaf(w, v.z, acc.z); acc.w = fmaf(w, v.w, acc.w);
        }
        __syncthreads();
    }
    if (valid) {
        float dn = g_dis[node];
        float4 hv = *(const float4*)(h + (size_t)node * F_H + t * 4);
        const float4 bv = *(const float4*)(bias + t * 4);
        float r[4] = {
            dn * fmaf(dn, hv.x, acc.x) + bv.x,
            dn * fmaf(dn, hv.y, acc.y) + bv.y,
            dn * fmaf(dn, hv.z, acc.z) + bv.z,
            dn * fmaf(dn, hv.w, acc.w) + bv.w };
        __nv_bfloat16 hi[4], lo[4];
        #pragma unroll
        for (int q = 0; q < 4; q++) {
            float v = r[q] > 0.f ? r[q] : 0.01f * r[q];
            split_bf16(v, hi[q], lo[q]);
        }
        __nv_bfloat162 hh0 = __halves2bfloat162(hi[0], hi[1]);
        __nv_bfloat162 hh1 = __halves2bfloat162(hi[2], hi[3]);
        __nv_bfloat162 ll0 = __halves2bfloat162(lo[0], lo[1]);
        __nv_bfloat162 ll1 = __halves2bfloat162(lo[2], lo[3]);
        *(uint2*)(ohi + (size_t)node * F_H + t * 4) = make_uint2(*(uint32_t*)&hh0, *(uint32_t*)&hh1);
        *(uint2*)(olo + (size_t)node * F_H + t * 4) = make_uint2(*(uint32_t*)&ll0, *(uint32_t*)&ll1);
    }
}

// last layer: agg (F=64) + bias + softmax. 16 threads x float4 per node, 16 nodes per block.
__global__ void __launch_bounds__(256)
agg_softmax_kernel(const float* __restrict__ h,
                   const float* __restrict__ bias,
                   float* __restrict__ out) {
    int g = threadIdx.x >> 4;     // node group 0..15
    int t = threadIdx.x & 15;     // thread in group
    int node = blockIdx.x * 16 + g;
    bool valid = node < N_NODES;

    float4 acc = make_float4(0.f, 0.f, 0.f, 0.f);
    if (valid) {
        int beg = g_rowptr[node], end = g_rowptr[node + 1];
        for (int e = beg; e < end; e++) {
            float w = g_csrw[e];
            float4 v = __ldg((const float4*)(h + (size_t)g_csr[e] * 64 + t * 4));
            acc.x = fmaf(w, v.x, acc.x); acc.y = fmaf(w, v.y, acc.y);
            acc.z = fmaf(w, v.z, acc.z); acc.w = fmaf(w, v.w, acc.w);
        }
        float dn = g_dis[node];
        float4 hv = *(const float4*)(h + (size_t)node * 64 + t * 4);
        const float4 bv = *(const float4*)(bias + t * 4);
        acc.x = dn * fmaf(dn, hv.x, acc.x) + bv.x;
        acc.y = dn * fmaf(dn, hv.y, acc.y) + bv.y;
        acc.z = dn * fmaf(dn, hv.z, acc.z) + bv.z;
        acc.w = dn * fmaf(dn, hv.w, acc.w) + bv.w;
    }
    float m = fmaxf(fmaxf(acc.x, acc.y), fmaxf(acc.z, acc.w));
    #pragma unroll
    for (int off = 8; off > 0; off >>= 1)
        m = fmaxf(m, __shfl_xor_sync(0xffffffffu, m, off, 16));
    float ex = expf(acc.x - m), ey = expf(acc.y - m);
    float ez = expf(acc.z - m), ew = expf(acc.w - m);
    float s = ex + ey + ez + ew;
    #pragma unroll
    for (int off = 8; off > 0; off >>= 1)
        s += __shfl_xor_sync(0xffffffffu, s, off, 16);
    if (valid) {
        float inv = 1.f / s;
        *(float4*)(out + (size_t)node * 64 + t * 4) = make_float4(ex * inv, ey * inv, ez * inv, ew * inv);
    }
}

// ---------------- launch ----------------
extern "C" void kernel_launch(void* const* d_in, const int* in_sizes, int n_in,
                              void* d_out, int out_size) {
    const float* x  = (const float*)d_in[0];
    const int*   ei = (const int*)  d_in[1];
    const float* W0 = (const float*)d_in[2];
    const float* b0 = (const float*)d_in[3];
    const float* W1 = (const float*)d_in[4];
    const float* b1 = (const float*)d_in[5];
    const float* W2 = (const float*)d_in[6];
    const float* b2 = (const float*)d_in[7];
    const float* W3 = (const float*)d_in[8];
    const float* b3 = (const float*)d_in[9];
    float* out = (float*)d_out;

    __nv_bfloat16 *ahi, *alo, *whibase, *wlobase;
    float* gout;
    cudaGetSymbolAddress((void**)&ahi, g_ahi);
    cudaGetSymbolAddress((void**)&alo, g_alo);
    cudaGetSymbolAddress((void**)&whibase, g_whi);
    cudaGetSymbolAddress((void**)&wlobase, g_wlo);
    cudaGetSymbolAddress((void**)&gout, g_gout);
    const size_t WSTRIDE = (size_t)F_IN * F_H;

    const int SM128 = 20480 + 2 * 128 * 80;          // per buffer
    const int SM64  = 20480 + 2 * 64 * 80;
    cudaFuncSetAttribute(mma_gemm_kernel<128>, cudaFuncAttributeMaxDynamicSharedMemorySize, 2 * SM128);
    cudaFuncSetAttribute(mma_gemm_kernel<64>,  cudaFuncAttributeMaxDynamicSharedMemorySize, 2 * SM64);

    const int TB = 256;
    int nblk_nodes = (N_NODES + TB - 1) / TB;
    int nblk_edges = (N_EDGES + TB - 1) / TB;
    int scan_blks = (N_NODES + 1023) / 1024;
    int mtiles = (N_NODES + 127) / 128;

    // launch order: gemm0 is the 4th launch (ncu capture window)
    pack_x_kernel<<<(N_NODES * F_IN / 4 + TB - 1) / TB, TB>>>(x, ahi, alo, N_NODES * F_IN / 4);
    pack_w_kernel<<<(F_IN * F_H + TB - 1) / TB, TB>>>(W0, whibase, wlobase, F_IN, F_H);
    pack_w_kernel<<<(F_H * F_H + TB - 1) / TB, TB>>>(W1, whibase + WSTRIDE, wlobase + WSTRIDE, F_H, F_H);

    // Layer 0 GEMM: 512 -> 256  (4th launch -> profiled)
    mma_gemm_kernel<128><<<dim3(2, mtiles), TB, 2 * SM128>>>(ahi, alo, whibase, wlobase, gout,
                                                             N_NODES, F_H, F_IN);

    pack_w_kernel<<<(F_H * F_H + TB - 1) / TB, TB>>>(W2, whibase + 2 * WSTRIDE, wlobase + 2 * WSTRIDE, F_H, F_H);
    pack_w_kernel<<<(F_H * F_OUT + TB - 1) / TB, TB>>>(W3, whibase + 3 * WSTRIDE, wlobase + 3 * WSTRIDE, F_H, F_OUT);

    // CSR build
    zero_kernel<<<nblk_nodes, TB>>>();
    count_kernel<<<nblk_edges, TB>>>(ei);
    dis_kernel<<<nblk_nodes, TB>>>();
    scan1_kernel<<<scan_blks, 1024>>>();
    scan2_kernel<<<1, 32>>>(scan_blks);
    scan3_kernel<<<scan_blks, 1024>>>();
    scatter_kernel<<<nblk_edges, TB>>>(ei);

    agg_pack_kernel<<<(N_NODES + 3) / 4, TB>>>(gout, b0, ahi, alo);
    // Layer 1
    mma_gemm_kernel<128><<<dim3(2, mtiles), TB, 2 * SM128>>>(ahi, alo, whibase + WSTRIDE, wlobase + WSTRIDE,
                                                             gout, N_NODES, F_H, F_H);
    agg_pack_kernel<<<(N_NODES + 3) / 4, TB>>>(gout, b1, ahi, alo);
    // Layer 2
    mma_gemm_kernel<128><<<dim3(2, mtiles), TB, 2 * SM128>>>(ahi, alo, whibase + 2 * WSTRIDE, wlobase + 2 * WSTRIDE,
                                                             gout, N_NODES, F_H, F_H);
    agg_pack_kernel<<<(N_NODES + 3) / 4, TB>>>(gout, b2, ahi, alo);
    // Layer 3: 256 -> 64 + softmax
    mma_gemm_kernel<64><<<dim3(1, mtiles), TB, 2 * SM64>>>(ahi, alo, whibase + 3 * WSTRIDE, wlobase + 3 * WSTRIDE,
                                                           gout, N_NODES, F_OUT, F_H);
    agg_softmax_kernel<<<(N_NODES + 15) / 16, TB>>>(gout, b3, out);
}

// round 8
// speedup vs baseline: 2.1581x; 1.0451x over previous
#include <cuda_runtime.h>
#include <cuda_bf16.h>
#include <math.h>
#include <cstdint>

#define N_NODES 100000
#define N_EDGES 3200000
#define F_IN    512
#define F_H     256
#define F_OUT   64

// ---------------- scratch (device globals: no alloc allowed) ----------------
__device__ int   g_deg[N_NODES];
__device__ int   g_cursor[N_NODES];
__device__ int   g_rowptr[N_NODES + 1];
__device__ float g_dis[N_NODES];
__device__ int   g_csr[N_EDGES];
__device__ float g_csrw[N_EDGES];       // per-edge weight dis[src]
__device__ int   g_blksum[128];
__device__ int   g_blkoff[128];
__device__ __nv_bfloat16 g_ahi[(size_t)N_NODES * F_IN];   // activation hi plane
__device__ __nv_bfloat16 g_alo[(size_t)N_NODES * F_IN];   // activation lo plane
__device__ float g_gout[(size_t)N_NODES * F_H];           // GEMM output (pre-agg) fp32
__device__ __nv_bfloat16 g_whi[4][(size_t)F_IN * F_H];    // W^T hi plane [N][K]
__device__ __nv_bfloat16 g_wlo[4][(size_t)F_IN * F_H];    // W^T lo plane [N][K]

// ---------------- packing helpers ----------------
__device__ __forceinline__ void split_bf16(float v, __nv_bfloat16& hi, __nv_bfloat16& lo) {
    hi = __float2bfloat16(v);
    lo = __float2bfloat16(v - __bfloat162float(hi));
}

__global__ void pack_x_kernel(const float* __restrict__ x,
                              __nv_bfloat16* __restrict__ hi,
                              __nv_bfloat16* __restrict__ lo, int n4) {
    int i = blockIdx.x * blockDim.x + threadIdx.x;
    if (i < n4) {
        float4 v = *(const float4*)(x + (size_t)i * 4);
        __nv_bfloat16 h0, l0, h1, l1, h2, l2, h3, l3;
        split_bf16(v.x, h0, l0); split_bf16(v.y, h1, l1);
        split_bf16(v.z, h2, l2); split_bf16(v.w, h3, l3);
        __nv_bfloat162 hh0 = __halves2bfloat162(h0, h1);
        __nv_bfloat162 hh1 = __halves2bfloat162(h2, h3);
        __nv_bfloat162 ll0 = __halves2bfloat162(l0, l1);
        __nv_bfloat162 ll1 = __halves2bfloat162(l2, l3);
        *(uint2*)(hi + (size_t)i * 4) = make_uint2(*(uint32_t*)&hh0, *(uint32_t*)&hh1);
        *(uint2*)(lo + (size_t)i * 4) = make_uint2(*(uint32_t*)&ll0, *(uint32_t*)&ll1);
    }
}

// W [K,N] fp32 -> W^T planes [N][K]
__global__ void pack_w_kernel(const float* __restrict__ W,
                              __nv_bfloat16* __restrict__ hi,
                              __nv_bfloat16* __restrict__ lo, int K, int N) {
    int i = blockIdx.x * blockDim.x + threadIdx.x;
    if (i < K * N) {
        int k = i / N, n = i % N;
        __nv_bfloat16 h, l;
        split_bf16(W[i], h, l);
        hi[(size_t)n * K + k] = h;
        lo[(size_t)n * K + k] = l;
    }
}

// ---------------- CSR build ----------------
__global__ void zero_kernel() {
    int i = blockIdx.x * blockDim.x + threadIdx.x;
    if (i < N_NODES) { g_deg[i] = 0; g_cursor[i] = 0; }
}
__global__ void count_kernel(const int* __restrict__ ei) {
    int e = blockIdx.x * blockDim.x + threadIdx.x;
    if (e < N_EDGES) atomicAdd(&g_deg[ei[N_EDGES + e]], 1);
}
__global__ void dis_kernel() {
    int n = blockIdx.x * blockDim.x + threadIdx.x;
    if (n < N_NODES) g_dis[n] = rsqrtf((float)g_deg[n] + 1.0f);
}
__global__ void scan1_kernel() {
    __shared__ int sh[1024];
    int tid = threadIdx.x;
    int idx = blockIdx.x * 1024 + tid;
    int v = (idx < N_NODES) ? g_deg[idx] : 0;
    sh[tid] = v;
    __syncthreads();
    #pragma unroll
    for (int off = 1; off < 1024; off <<= 1) {
        int t = (tid >= off) ? sh[tid - off] : 0;
        __syncthreads();
        sh[tid] += t;
        __syncthreads();
    }
    if (idx < N_NODES) g_rowptr[idx] = sh[tid] - v;
    if (tid == 1023) g_blksum[blockIdx.x] = sh[1023];
}
__global__ void scan2_kernel(int nblk) {
    if (threadIdx.x == 0) {
        int run = 0;
        for (int b = 0; b < nblk; b++) { int t = g_blksum[b]; g_blkoff[b] = run; run += t; }
        g_rowptr[N_NODES] = run;
    }
}
__global__ void scan3_kernel() {
    int idx = blockIdx.x * 1024 + threadIdx.x;
    if (idx < N_NODES) g_rowptr[idx] += g_blkoff[blockIdx.x];
}
__global__ void scatter_kernel(const int* __restrict__ ei) {
    int e = blockIdx.x * blockDim.x + threadIdx.x;
    if (e < N_EDGES) {
        int d = ei[N_EDGES + e];
        int s = ei[e];
        int pos = atomicAdd(&g_cursor[d], 1);
        int slot = g_rowptr[d] + pos;
        g_csr[slot] = s;
        g_csrw[slot] = g_dis[s];
    }
}

// ---------------- mma.sync bf16 GEMM: C[M,N] = A[M,K] @ W[K,N] (W^T planes given) ----------------
// fp32 emulation: C = Ah*Bh + Al*Bh + Ah*Bl. BM=128, BN template, BK=32.
// 8 warps: 4 in M x 2 in N. cp.async double-buffered; A frags ldmatrix.x4, B frags x4 (tile pairs).
// B hi/lo fragments share registers (two phases per k-step) -> <=128 regs -> 2 CTAs/SM.
__device__ __forceinline__ void cp_async16(uint32_t dst, const void* src, int szr) {
    asm volatile("cp.async.ca.shared.global [%0], [%1], 16, %2;"
                 :: "r"(dst), "l"(src), "r"(szr));
}
__device__ __forceinline__ void mma16816(float* c, const uint32_t* a, const uint32_t* b) {
    asm volatile(
        "mma.sync.aligned.m16n8k16.row.col.f32.bf16.bf16.f32 "
        "{%0,%1,%2,%3}, {%4,%5,%6,%7}, {%8,%9}, {%0,%1,%2,%3};"
        : "+f"(c[0]), "+f"(c[1]), "+f"(c[2]), "+f"(c[3])
        : "r"(a[0]), "r"(a[1]), "r"(a[2]), "r"(a[3]), "r"(b[0]), "r"(b[1]));
}
__device__ __forceinline__ void ldsm_x4(uint32_t* r, uint32_t addr) {
    asm volatile("ldmatrix.sync.aligned.m8n8.x4.shared.b16 {%0,%1,%2,%3}, [%4];"
        : "=r"(r[0]), "=r"(r[1]), "=r"(r[2]), "=r"(r[3]) : "r"(addr));
}

template<int BN>
__global__ void __launch_bounds__(256, 2)
mma_gemm_kernel(const __nv_bfloat16* __restrict__ Ahi, const __nv_bfloat16* __restrict__ Alo,
                const __nv_bfloat16* __restrict__ Bhi, const __nv_bfloat16* __restrict__ Blo,
                float* __restrict__ C, int M, int N, int K) {
    extern __shared__ char smem[];
    // per buffer: A_hi [0,10240) A_lo [10240,20480) B_hi [20480,+BN*80) B_lo follows
    const int BSZ = BN * 80;
    const int BUF = 20480 + 2 * BSZ;
    const int NT = BN / 16;               // n8 tiles per warp (warp covers BN/2 cols)
    uint32_t sbase;
    asm("{ .reg .u64 t; cvta.to.shared.u64 t, %1; cvt.u32.u64 %0, t; }"
        : "=r"(sbase) : "l"(smem));

    int tid = threadIdx.x, lane = tid & 31, wid = tid >> 5;
    int gID = lane >> 2, tig = lane & 3;
    int warpM = (wid & 3) * 32, warpN = (wid >> 2) * (BN / 2);
    int bm = blockIdx.y * 128, bn = blockIdx.x * BN;

    // A x4 lane offset: rows (lane&7)+((lane>>3)&1)*8, k-half (lane>>4)*16B
    uint32_t aOff = (uint32_t)((warpM + (lane & 7) + ((lane >> 3) & 1) * 8) * 80
                               + (lane >> 4) * 16);
    // B x4 lane offset (two n8 tiles per op): m0=(p,k0) m1=(p,k1) m2=(p+1,k0) m3=(p+1,k1)
    uint32_t b4Off = (uint32_t)((warpN + ((lane >> 4) << 3) + (lane & 7)) * 80
                                + ((lane >> 3) & 1) * 16);

    float acc[2][NT][4];
    #pragma unroll
    for (int i = 0; i < 2; i++)
        #pragma unroll
        for (int j = 0; j < NT; j++)
            #pragma unroll
            for (int q = 0; q < 4; q++) acc[i][j][q] = 0.f;

    int nch = K >> 5;

    auto load_tile = [&](int buf, int c) {
        uint32_t bb = sbase + buf * BUF;
        #pragma unroll
        for (int it = 0; it < 4; it++) {
            int idx = tid + it * 256;
            int ch = idx & 3, r = (idx >> 2) & 127, pl = idx >> 9;
            int row = bm + r;
            int szr = (row < M) ? 16 : 0;
            int rowc = (row < M) ? row : (M - 1);
            const __nv_bfloat16* src = (pl ? Alo : Ahi) + (size_t)rowc * K + c * 32 + ch * 8;
            cp_async16(bb + pl * 10240 + r * 80 + ch * 16, src, szr);
        }
        #pragma unroll
        for (int it = 0; it < BN / 32; it++) {
            int idx = tid + it * 256;
            int ch = idx & 3, r = (idx >> 2) % BN, pl = idx / (BN * 4);
            const __nv_bfloat16* src = (pl ? Blo : Bhi) + (size_t)(bn + r) * K + c * 32 + ch * 8;
            cp_async16(bb + 20480 + pl * BSZ + r * 80 + ch * 16, src, 16);
        }
    };

    load_tile(0, 0);
    asm volatile("cp.async.commit_group;");

    for (int c = 0; c < nch; c++) {
        if (c + 1 < nch) load_tile((c + 1) & 1, c + 1);
        asm volatile("cp.async.commit_group;");
        asm volatile("cp.async.wait_group 1;");
        __syncthreads();

        uint32_t bufb = sbase + (c & 1) * BUF;
        uint32_t aHi = bufb + aOff;
        uint32_t aLo = aHi + 10240;
        uint32_t bHi = bufb + 20480 + b4Off;
        uint32_t bLo = bHi + BSZ;

        #pragma unroll
        for (int ks = 0; ks < 2; ks++) {
            uint32_t ah[2][4], al[2][4], bb2[NT][2];
            #pragma unroll
            for (int mt = 0; mt < 2; mt++) {
                ldsm_x4(ah[mt], aHi + mt * (16 * 80) + ks * 32);
                ldsm_x4(al[mt], aLo + mt * (16 * 80) + ks * 32);
            }
            // phase 1: B hi plane -> ah*bh + al*bh
            #pragma unroll
            for (int p = 0; p < NT / 2; p++)
                ldsm_x4(&bb2[2 * p][0], bHi + p * (16 * 80) + ks * 32);
            #pragma unroll
            for (int mt = 0; mt < 2; mt++)
                #pragma unroll
                for (int nt = 0; nt < NT; nt++) {
                    mma16816(acc[mt][nt], ah[mt], bb2[nt]);
                    mma16816(acc[mt][nt], al[mt], bb2[nt]);
                }
            // phase 2: B lo plane -> ah*bl (reuse bb2 registers)
            #pragma unroll
            for (int p = 0; p < NT / 2; p++)
                ldsm_x4(&bb2[2 * p][0], bLo + p * (16 * 80) + ks * 32);
            #pragma unroll
            for (int mt = 0; mt < 2; mt++)
                #pragma unroll
                for (int nt = 0; nt < NT; nt++)
                    mma16816(acc[mt][nt], ah[mt], bb2[nt]);
        }
        __syncthreads();
    }

    // epilogue: direct register -> global
    #pragma unroll
    for (int mt = 0; mt < 2; mt++) {
        int row0 = bm + warpM + mt * 16 + gID;
        #pragma unroll
        for (int nt = 0; nt < NT; nt++) {
            int col = bn + warpN + nt * 8 + tig * 2;
            if (row0 < M)
                *(float2*)(C + (size_t)row0 * N + col) = make_float2(acc[mt][nt][0], acc[mt][nt][1]);
            if (row0 + 8 < M)
                *(float2*)(C + (size_t)(row0 + 8) * N + col) = make_float2(acc[mt][nt][2], acc[mt][nt][3]);
        }
    }
}

// ---------------- aggregation: float4 gather, 4 nodes per 256-thread block ----------------
__global__ void __launch_bounds__(256)
agg_pack_kernel(const float* __restrict__ h,
                const float* __restrict__ bias,
                __nv_bfloat16* __restrict__ ohi,
                __nv_bfloat16* __restrict__ olo) {
    __shared__ int   sE[4][64];
    __shared__ float sW[4][64];
    int g = threadIdx.x >> 6;      // node group 0..3
    int t = threadIdx.x & 63;      // thread in group
    int node = blockIdx.x * 4 + g;
    bool valid = node < N_NODES;

    int beg = 0, end = 0;
    if (valid) { beg = g_rowptr[node]; end = g_rowptr[node + 1]; }
    float4 acc = make_float4(0.f, 0.f, 0.f, 0.f);

    for (int cs = beg; cs < end; cs += 64) {
        int cnt = min(64, end - cs);
        if (t < cnt) { sE[g][t] = g_csr[cs + t]; sW[g][t] = g_csrw[cs + t]; }
        __syncthreads();
        #pragma unroll 2
        for (int i = 0; i < cnt; i++) {
            float w = sW[g][i];
            float4 v = __ldg((const float4*)(h + (size_t)sE[g][i] * F_H + t * 4));
            acc.x = fmaf(w, v.x, acc.x); acc.y = fmaf(w, v.y, acc.y);
            acc.z = fmaf(w, v.z, acc.z); acc.w = fmaf(w, v.w, acc.w);
        }
        __syncthreads();
    }
    if (valid) {
        float dn = g_dis[node];
        float4 hv = *(const float4*)(h + (size_t)node * F_H + t * 4);
        const float4 bv = *(const float4*)(bias + t * 4);
        float r[4] = {
            dn * fmaf(dn, hv.x, acc.x) + bv.x,
            dn * fmaf(dn, hv.y, acc.y) + bv.y,
            dn * fmaf(dn, hv.z, acc.z) + bv.z,
            dn * fmaf(dn, hv.w, acc.w) + bv.w };
        __nv_bfloat16 hi[4], lo[4];
        #pragma unroll
        for (int q = 0; q < 4; q++) {
            float v = r[q] > 0.f ? r[q] : 0.01f * r[q];
            split_bf16(v, hi[q], lo[q]);
        }
        __nv_bfloat162 hh0 = __halves2bfloat162(hi[0], hi[1]);
        __nv_bfloat162 hh1 = __halves2bfloat162(hi[2], hi[3]);
        __nv_bfloat162 ll0 = __halves2bfloat162(lo[0], lo[1]);
        __nv_bfloat162 ll1 = __halves2bfloat162(lo[2], lo[3]);
        *(uint2*)(ohi + (size_t)node * F_H + t * 4) = make_uint2(*(uint32_t*)&hh0, *(uint32_t*)&hh1);
        *(uint2*)(olo + (size_t)node * F_H + t * 4) = make_uint2(*(uint32_t*)&ll0, *(uint32_t*)&ll1);
    }
}

// last layer: agg (F=64) + bias + softmax. 16 threads x float4 per node, 16 nodes per block.
__global__ void __launch_bounds__(256)
agg_softmax_kernel(const float* __restrict__ h,
                   const float* __restrict__ bias,
                   float* __restrict__ out) {
    int g = threadIdx.x >> 4;     // node group 0..15
    int t = threadIdx.x & 15;     // thread in group
    int node = blockIdx.x * 16 + g;
    bool valid = node < N_NODES;

    float4 acc = make_float4(0.f, 0.f, 0.f, 0.f);
    if (valid) {
        int beg = g_rowptr[node], end = g_rowptr[node + 1];
        for (int e = beg; e < end; e++) {
            float w = g_csrw[e];
            float4 v = __ldg((const float4*)(h + (size_t)g_csr[e] * 64 + t * 4));
            acc.x = fmaf(w, v.x, acc.x); acc.y = fmaf(w, v.y, acc.y);
            acc.z = fmaf(w, v.z, acc.z); acc.w = fmaf(w, v.w, acc.w);
        }
        float dn = g_dis[node];
        float4 hv = *(const float4*)(h + (size_t)node * 64 + t * 4);
        const float4 bv = *(const float4*)(bias + t * 4);
        acc.x = dn * fmaf(dn, hv.x, acc.x) + bv.x;
        acc.y = dn * fmaf(dn, hv.y, acc.y) + bv.y;
        acc.z = dn * fmaf(dn, hv.z, acc.z) + bv.z;
        acc.w = dn * fmaf(dn, hv.w, acc.w) + bv.w;
    }
    float m = fmaxf(fmaxf(acc.x, acc.y), fmaxf(acc.z, acc.w));
    #pragma unroll
    for (int off = 8; off > 0; off >>= 1)
        m = fmaxf(m, __shfl_xor_sync(0xffffffffu, m, off, 16));
    float ex = expf(acc.x - m), ey = expf(acc.y - m);
    float ez = expf(acc.z - m), ew = expf(acc.w - m);
    float s = ex + ey + ez + ew;
    #pragma unroll
    for (int off = 8; off > 0; off >>= 1)
        s += __shfl_xor_sync(0xffffffffu, s, off, 16);
    if (valid) {
        float inv = 1.f / s;
        *(float4*)(out + (size_t)node * 64 + t * 4) = make_float4(ex * inv, ey * inv, ez * inv, ew * inv);
    }
}

// ---------------- launch ----------------
extern "C" void kernel_launch(void* const* d_in, const int* in_sizes, int n_in,
                              void* d_out, int out_size) {
    const float* x  = (const float*)d_in[0];
    const int*   ei = (const int*)  d_in[1];
    const float* W0 = (const float*)d_in[2];
    const float* b0 = (const float*)d_in[3];
    const float* W1 = (const float*)d_in[4];
    const float* b1 = (const float*)d_in[5];
    const float* W2 = (const float*)d_in[6];
    const float* b2 = (const float*)d_in[7];
    const float* W3 = (const float*)d_in[8];
    const float* b3 = (const float*)d_in[9];
    float* out = (float*)d_out;

    __nv_bfloat16 *ahi, *alo, *whibase, *wlobase;
    float* gout;
    cudaGetSymbolAddress((void**)&ahi, g_ahi);
    cudaGetSymbolAddress((void**)&alo, g_alo);
    cudaGetSymbolAddress((void**)&whibase, g_whi);
    cudaGetSymbolAddress((void**)&wlobase, g_wlo);
    cudaGetSymbolAddress((void**)&gout, g_gout);
    const size_t WSTRIDE = (size_t)F_IN * F_H;

    const int SM128 = 20480 + 2 * 128 * 80;          // per buffer
    const int SM64  = 20480 + 2 * 64 * 80;
    cudaFuncSetAttribute(mma_gemm_kernel<128>, cudaFuncAttributeMaxDynamicSharedMemorySize, 2 * SM128);
    cudaFuncSetAttribute(mma_gemm_kernel<64>,  cudaFuncAttributeMaxDynamicSharedMemorySize, 2 * SM64);

    // capture-safe fork/join resources (created once; reused every call)
    static cudaStream_t s2 = []{
        cudaStream_t s; cudaStreamCreateWithFlags(&s, cudaStreamNonBlocking); return s; }();
    static cudaEvent_t evFork = []{
        cudaEvent_t e; cudaEventCreateWithFlags(&e, cudaEventDisableTiming); return e; }();
    static cudaEvent_t evJoin = []{
        cudaEvent_t e; cudaEventCreateWithFlags(&e, cudaEventDisableTiming); return e; }();

    const int TB = 256;
    int nblk_nodes = (N_NODES + TB - 1) / TB;
    int nblk_edges = (N_EDGES + TB - 1) / TB;
    int scan_blks = (N_NODES + 1023) / 1024;
    int mtiles = (N_NODES + 127) / 128;

    // fork: CSR build on s2, concurrent with packing + gemm0 on main stream
    cudaEventRecord(evFork, 0);
    cudaStreamWaitEvent(s2, evFork, 0);

    zero_kernel<<<nblk_nodes, TB, 0, s2>>>();
    count_kernel<<<nblk_edges, TB, 0, s2>>>(ei);
    dis_kernel<<<nblk_nodes, TB, 0, s2>>>();
    scan1_kernel<<<scan_blks, 1024, 0, s2>>>();
    scan2_kernel<<<1, 32, 0, s2>>>(scan_blks);
    scan3_kernel<<<scan_blks, 1024, 0, s2>>>();
    scatter_kernel<<<nblk_edges, TB, 0, s2>>>(ei);
    cudaEventRecord(evJoin, s2);

    // main stream: packs + gemm0
    pack_x_kernel<<<(N_NODES * F_IN / 4 + TB - 1) / TB, TB>>>(x, ahi, alo, N_NODES * F_IN / 4);
    pack_w_kernel<<<(F_IN * F_H + TB - 1) / TB, TB>>>(W0, whibase, wlobase, F_IN, F_H);
    pack_w_kernel<<<(F_H * F_H + TB - 1) / TB, TB>>>(W1, whibase + WSTRIDE, wlobase + WSTRIDE, F_H, F_H);
    mma_gemm_kernel<128><<<dim3(2, mtiles), TB, 2 * SM128>>>(ahi, alo, whibase, wlobase, gout,
                                                             N_NODES, F_H, F_IN);
    pack_w_kernel<<<(F_H * F_H + TB - 1) / TB, TB>>>(W2, whibase + 2 * WSTRIDE, wlobase + 2 * WSTRIDE, F_H, F_H);
    pack_w_kernel<<<(F_H * F_OUT + TB - 1) / TB, TB>>>(W3, whibase + 3 * WSTRIDE, wlobase + 3 * WSTRIDE, F_H, F_OUT);

    // join: aggregation needs the CSR
    cudaStreamWaitEvent(0, evJoin, 0);

    agg_pack_kernel<<<(N_NODES + 3) / 4, TB>>>(gout, b0, ahi, alo);
    // Layer 1
    mma_gemm_kernel<128><<<dim3(2, mtiles), TB, 2 * SM128>>>(ahi, alo, whibase + WSTRIDE, wlobase + WSTRIDE,
                                                             gout, N_NODES, F_H, F_H);
    agg_pack_kernel<<<(N_NODES + 3) / 4, TB>>>(gout, b1, ahi, alo);
    // Layer 2
    mma_gemm_kernel<128><<<dim3(2, mtiles), TB, 2 * SM128>>>(ahi, alo, whibase + 2 * WSTRIDE, wlobase + 2 * WSTRIDE,
                                                             gout, N_NODES, F_H, F_H);
    agg_pack_kernel<<<(N_NODES + 3) / 4, TB>>>(gout, b2, ahi, alo);
    // Layer 3: 256 -> 64 + softmax
    mma_gemm_kernel<64><<<dim3(1, mtiles), TB, 2 * SM64>>>(ahi, alo, whibase + 3 * WSTRIDE, wlobase + 3 * WSTRIDE,
                                                           gout, N_NODES, F_OUT, F_H);
    agg_softmax_kernel<<<(N_NODES + 15) / 16, TB>>>(gout, b3, out);
}